// round 2
// baseline (speedup 1.0000x reference)
#include <cuda_runtime.h>
#include <cuda_bf16.h>
#include <math.h>

#define NN 512
#define CC 128
#define NPOS (NN*NN)           // 262144 positions

// Scratch planes (channel-major): a_s[c][i][k], b_s[c][j][k], tri_s[c][i][j]
__device__ float g_a[(size_t)CC * NPOS];
__device__ float g_b[(size_t)CC * NPOS];
__device__ float g_t[(size_t)CC * NPOS];

// ---------------------------------------------------------------------------
// Kernel A: LN1 + proj/gate GEMM + mask*sigmoid gating + de-interleave
// Block: 256 threads, 64 positions. Dynamic smem:
//   xs   : 64 x 129 floats   (LN'd input rows)
//   wp_s : 128 x 68 floats   (Wp chunk, transposed [k][o_local]) -- also reused as staging
//   wg_s : 128 x 68 floats   (Wg chunk, transposed)
// ---------------------------------------------------------------------------
#define KA_SMEM ((64*129 + 2*128*68) * sizeof(float))

__global__ void __launch_bounds__(256) kA(const float* __restrict__ pair,
                                          const float* __restrict__ mask,
                                          const float* __restrict__ w1,
                                          const float* __restrict__ b1,
                                          const float* __restrict__ Wp,
                                          const float* __restrict__ Wg)
{
    extern __shared__ float sm[];
    float* xs   = sm;                    // 64*129
    float* wp_s = xs + 64*129;           // 128*68
    float* wg_s = wp_s + 128*68;         // 128*68
    __shared__ float mrow[64];

    const int tid = threadIdx.x;
    const int p0  = blockIdx.x * 64;

    // Load 64x128 pair values (contiguous) into xs
    #pragma unroll
    for (int it = 0; it < 32; ++it) {
        int idx = it*256 + tid;          // 0..8191
        int r = idx >> 7, c = idx & 127;
        xs[r*129 + c] = pair[(size_t)p0*CC + idx];
    }
    if (tid < 64) mrow[tid] = mask[p0 + tid];
    __syncthreads();

    // LN1: 8 warps x 8 rows each
    const int warp = tid >> 5, lane = tid & 31;
    for (int rr = 0; rr < 8; ++rr) {
        int r = warp*8 + rr;
        float v0 = xs[r*129 + lane      ];
        float v1 = xs[r*129 + lane + 32 ];
        float v2 = xs[r*129 + lane + 64 ];
        float v3 = xs[r*129 + lane + 96 ];
        float s  = v0+v1+v2+v3;
        float s2 = v0*v0+v1*v1+v2*v2+v3*v3;
        #pragma unroll
        for (int o = 16; o; o >>= 1) {
            s  += __shfl_xor_sync(0xffffffffu, s , o);
            s2 += __shfl_xor_sync(0xffffffffu, s2, o);
        }
        float mu   = s * (1.f/128.f);
        float var  = s2 * (1.f/128.f) - mu*mu;
        float rstd = rsqrtf(var + 1e-5f);
        xs[r*129 + lane      ] = (v0-mu)*rstd*w1[lane     ] + b1[lane     ];
        xs[r*129 + lane + 32 ] = (v1-mu)*rstd*w1[lane + 32] + b1[lane + 32];
        xs[r*129 + lane + 64 ] = (v2-mu)*rstd*w1[lane + 64] + b1[lane + 64];
        xs[r*129 + lane + 96 ] = (v3-mu)*rstd*w1[lane + 96] + b1[lane + 96];
    }
    __syncthreads();

    const int tx = tid & 15;   // output-col group (4 cols)
    const int ty = tid >> 4;   // row group (4 rows)

    for (int o0 = 0; o0 < 256; o0 += 64) {
        // Load weight chunk transposed: wp_s[k][r] = Wp[o0+r][k]
        #pragma unroll
        for (int it = 0; it < 32; ++it) {
            int idx = it*256 + tid;      // 0..8191
            int r = idx >> 7, k = idx & 127;
            wp_s[k*68 + r] = Wp[(o0 + r)*CC + k];
            wg_s[k*68 + r] = Wg[(o0 + r)*CC + k];
        }
        __syncthreads();

        float accP[4][4] = {}, accG[4][4] = {};
        #pragma unroll 4
        for (int k = 0; k < 128; ++k) {
            float xv[4];
            #pragma unroll
            for (int i = 0; i < 4; ++i) xv[i] = xs[(ty*4 + i)*129 + k];
            float4 pv = *(const float4*)&wp_s[k*68 + tx*4];
            float4 gv = *(const float4*)&wg_s[k*68 + tx*4];
            const float pvv[4] = {pv.x, pv.y, pv.z, pv.w};
            const float gvv[4] = {gv.x, gv.y, gv.z, gv.w};
            #pragma unroll
            for (int i = 0; i < 4; ++i)
                #pragma unroll
                for (int j = 0; j < 4; ++j) {
                    accP[i][j] = fmaf(xv[i], pvv[j], accP[i][j]);
                    accG[i][j] = fmaf(xv[i], gvv[j], accG[i][j]);
                }
        }
        __syncthreads();   // done reading weights; reuse wp_s as staging

        // Gate and stage (ts[r][c] at stride 65 inside wp_s)
        #pragma unroll
        for (int i = 0; i < 4; ++i)
            #pragma unroll
            for (int j = 0; j < 4; ++j) {
                int r = ty*4 + i, c = tx*4 + j;
                float sg = 1.f / (1.f + expf(-accG[i][j]));
                wp_s[r*65 + c] = accP[i][j] * mrow[r] * sg;
            }
        __syncthreads();

        // Coalesced scatter into channel planes
        #pragma unroll
        for (int it = 0; it < 16; ++it) {
            int idx = it*256 + tid;      // 0..4095
            int c = idx >> 6, r = idx & 63;
            int og = o0 + c;
            float v = wp_s[r*65 + c];
            float* dst = (og & 1) ? g_b : g_a;
            dst[(size_t)(og >> 1)*NPOS + p0 + r] = v;
        }
        __syncthreads();
    }
}

// ---------------------------------------------------------------------------
// Kernel B: per-channel NT SGEMM  T_c = A_c @ B_c^T, 512x512x512
// Block: 256 threads, 64x64 tile, BK=16, 4x4 micro-tile.
// ---------------------------------------------------------------------------
__global__ void __launch_bounds__(256) kB()
{
    const int c  = blockIdx.z;
    const float* __restrict__ A = g_a + (size_t)c * NPOS;
    const float* __restrict__ B = g_b + (size_t)c * NPOS;
    float* __restrict__ T = g_t + (size_t)c * NPOS;
    const int i0 = blockIdx.y * 64;
    const int j0 = blockIdx.x * 64;

    __shared__ float As[16][68];
    __shared__ float Bs[16][68];

    const int tid = threadIdx.x;
    const int tx = tid & 15, ty = tid >> 4;
    const int lr = tid >> 2;         // 0..63 (row within tile)
    const int lk = (tid & 3) * 4;    // 0,4,8,12

    float acc[4][4] = {};

    for (int k0 = 0; k0 < 512; k0 += 16) {
        float4 av = *(const float4*)&A[(size_t)(i0 + lr)*NN + k0 + lk];
        float4 bv = *(const float4*)&B[(size_t)(j0 + lr)*NN + k0 + lk];
        As[lk+0][lr] = av.x; As[lk+1][lr] = av.y; As[lk+2][lr] = av.z; As[lk+3][lr] = av.w;
        Bs[lk+0][lr] = bv.x; Bs[lk+1][lr] = bv.y; Bs[lk+2][lr] = bv.z; Bs[lk+3][lr] = bv.w;
        __syncthreads();
        #pragma unroll
        for (int kk = 0; kk < 16; ++kk) {
            float ar[4], br[4];
            #pragma unroll
            for (int i = 0; i < 4; ++i) ar[i] = As[kk][ty*4 + i];
            #pragma unroll
            for (int j = 0; j < 4; ++j) br[j] = Bs[kk][tx*4 + j];
            #pragma unroll
            for (int i = 0; i < 4; ++i)
                #pragma unroll
                for (int j = 0; j < 4; ++j)
                    acc[i][j] = fmaf(ar[i], br[j], acc[i][j]);
        }
        __syncthreads();
    }

    #pragma unroll
    for (int i = 0; i < 4; ++i) {
        float4 v = make_float4(acc[i][0], acc[i][1], acc[i][2], acc[i][3]);
        *(float4*)&T[(size_t)(i0 + ty*4 + i)*NN + j0 + tx*4] = v;
    }
}

// ---------------------------------------------------------------------------
// Kernel C: LN2(tri) @ Wo.T * sigmoid(LN1(pair) @ Wgl.T) + pair
// Block: 256 threads, 32 positions (one row i, 32 consecutive j).
// Dynamic smem: wo_s[128][132] (transposed [c][o]), wgl_s same,
//               t_sm[32][129], x_sm[32][129].
// ---------------------------------------------------------------------------
#define KC_SMEM ((2*128*132 + 2*32*129) * sizeof(float))

__global__ void __launch_bounds__(256) kC(const float* __restrict__ pair,
                                          const float* __restrict__ w1,
                                          const float* __restrict__ b1,
                                          const float* __restrict__ w2,
                                          const float* __restrict__ b2,
                                          const float* __restrict__ Wo,
                                          const float* __restrict__ Wgl,
                                          float* __restrict__ out)
{
    extern __shared__ float sm[];
    float* wo_s  = sm;                       // 128*132, [c][o]
    float* wgl_s = wo_s + 128*132;           // 128*132
    float* t_sm  = wgl_s + 128*132;          // 32*129
    float* x_sm  = t_sm + 32*129;            // 32*129

    const int tid = threadIdx.x;
    const int i   = blockIdx.y;
    const int j0  = blockIdx.x * 32;
    const size_t pbase = ((size_t)i*NN + j0) * CC;

    // Weights transposed into smem: wo_s[c*132 + o] = Wo[o][c]
    #pragma unroll
    for (int it = 0; it < 64; ++it) {
        int idx = it*256 + tid;              // 0..16383
        int o = idx >> 7, c = idx & 127;
        wo_s [c*132 + o] = Wo [idx];
        wgl_s[c*132 + o] = Wgl[idx];
    }
    // tri tile: t_sm[r][c] from plane-major g_t
    #pragma unroll
    for (int it = 0; it < 16; ++it) {
        int idx = it*256 + tid;              // 0..4095
        int c = idx >> 5, r = idx & 31;
        t_sm[r*129 + c] = g_t[(size_t)c*NPOS + (size_t)i*NN + j0 + r];
    }
    // pair tile
    #pragma unroll
    for (int it = 0; it < 16; ++it) {
        int idx = it*256 + tid;
        int r = idx >> 7, c = idx & 127;
        x_sm[r*129 + c] = pair[pbase + idx];
    }
    __syncthreads();

    // LN2 on t_sm, LN1 on x_sm: 8 warps x 4 rows
    const int warp = tid >> 5, lane = tid & 31;
    for (int rr = 0; rr < 4; ++rr) {
        int r = warp*4 + rr;
        {   // tri
            float v0 = t_sm[r*129+lane], v1 = t_sm[r*129+lane+32],
                  v2 = t_sm[r*129+lane+64], v3 = t_sm[r*129+lane+96];
            float s = v0+v1+v2+v3, s2 = v0*v0+v1*v1+v2*v2+v3*v3;
            #pragma unroll
            for (int o = 16; o; o >>= 1) {
                s  += __shfl_xor_sync(0xffffffffu, s , o);
                s2 += __shfl_xor_sync(0xffffffffu, s2, o);
            }
            float mu = s*(1.f/128.f), var = s2*(1.f/128.f) - mu*mu;
            float rstd = rsqrtf(var + 1e-5f);
            t_sm[r*129+lane   ] = (v0-mu)*rstd*w2[lane   ] + b2[lane   ];
            t_sm[r*129+lane+32] = (v1-mu)*rstd*w2[lane+32] + b2[lane+32];
            t_sm[r*129+lane+64] = (v2-mu)*rstd*w2[lane+64] + b2[lane+64];
            t_sm[r*129+lane+96] = (v3-mu)*rstd*w2[lane+96] + b2[lane+96];
        }
        {   // pair -> x
            float v0 = x_sm[r*129+lane], v1 = x_sm[r*129+lane+32],
                  v2 = x_sm[r*129+lane+64], v3 = x_sm[r*129+lane+96];
            float s = v0+v1+v2+v3, s2 = v0*v0+v1*v1+v2*v2+v3*v3;
            #pragma unroll
            for (int o = 16; o; o >>= 1) {
                s  += __shfl_xor_sync(0xffffffffu, s , o);
                s2 += __shfl_xor_sync(0xffffffffu, s2, o);
            }
            float mu = s*(1.f/128.f), var = s2*(1.f/128.f) - mu*mu;
            float rstd = rsqrtf(var + 1e-5f);
            x_sm[r*129+lane   ] = (v0-mu)*rstd*w1[lane   ] + b1[lane   ];
            x_sm[r*129+lane+32] = (v1-mu)*rstd*w1[lane+32] + b1[lane+32];
            x_sm[r*129+lane+64] = (v2-mu)*rstd*w1[lane+64] + b1[lane+64];
            x_sm[r*129+lane+96] = (v3-mu)*rstd*w1[lane+96] + b1[lane+96];
        }
    }
    __syncthreads();

    // GEMM: 32 rows x 128 outputs, both matrices. 8x32 thread grid, 4x4 micro.
    const int tx = tid & 31;   // col group (4 cols -> 128)
    const int ty = tid >> 5;   // row group (4 rows -> 32)
    float accO[4][4] = {}, accG[4][4] = {};
    #pragma unroll 4
    for (int c = 0; c < 128; ++c) {
        float tv[4], xv[4];
        #pragma unroll
        for (int ii = 0; ii < 4; ++ii) {
            tv[ii] = t_sm[(ty*4 + ii)*129 + c];
            xv[ii] = x_sm[(ty*4 + ii)*129 + c];
        }
        float4 wov = *(const float4*)&wo_s [c*132 + tx*4];
        float4 wgv = *(const float4*)&wgl_s[c*132 + tx*4];
        const float wo4[4] = {wov.x, wov.y, wov.z, wov.w};
        const float wg4[4] = {wgv.x, wgv.y, wgv.z, wgv.w};
        #pragma unroll
        for (int ii = 0; ii < 4; ++ii)
            #pragma unroll
            for (int jj = 0; jj < 4; ++jj) {
                accO[ii][jj] = fmaf(tv[ii], wo4[jj], accO[ii][jj]);
                accG[ii][jj] = fmaf(xv[ii], wg4[jj], accG[ii][jj]);
            }
    }

    // Combine + residual, float4 coalesced writes
    #pragma unroll
    for (int ii = 0; ii < 4; ++ii) {
        int r = ty*4 + ii;
        size_t rowb = pbase + (size_t)r*CC + tx*4;
        float4 pr = *(const float4*)&pair[rowb];
        float4 o4;
        o4.x = pr.x + accO[ii][0] * (1.f/(1.f+expf(-accG[ii][0])));
        o4.y = pr.y + accO[ii][1] * (1.f/(1.f+expf(-accG[ii][1])));
        o4.z = pr.z + accO[ii][2] * (1.f/(1.f+expf(-accG[ii][2])));
        o4.w = pr.w + accO[ii][3] * (1.f/(1.f+expf(-accG[ii][3])));
        *(float4*)&out[rowb] = o4;
    }
}

// ---------------------------------------------------------------------------
extern "C" void kernel_launch(void* const* d_in, const int* in_sizes, int n_in,
                              void* d_out, int out_size)
{
    const float* pair = (const float*)d_in[0];
    const float* mask = (const float*)d_in[1];
    const float* w1   = (const float*)d_in[2];
    const float* b1   = (const float*)d_in[3];
    const float* Wp   = (const float*)d_in[4];
    const float* Wg   = (const float*)d_in[5];
    const float* w2   = (const float*)d_in[6];
    const float* b2   = (const float*)d_in[7];
    const float* Wo   = (const float*)d_in[8];
    const float* Wgl  = (const float*)d_in[9];
    float* out = (float*)d_out;

    cudaFuncSetAttribute(kA, cudaFuncAttributeMaxDynamicSharedMemorySize, (int)KA_SMEM);
    cudaFuncSetAttribute(kC, cudaFuncAttributeMaxDynamicSharedMemorySize, (int)KC_SMEM);

    kA<<<NPOS/64, 256, KA_SMEM>>>(pair, mask, w1, b1, Wp, Wg);
    kB<<<dim3(NN/64, NN/64, CC), 256>>>();
    kC<<<dim3(NN/32, NN), 256, KC_SMEM>>>(pair, w1, b1, w2, b2, Wo, Wgl, out);
}

// round 3
// speedup vs baseline: 2.9229x; 2.9229x over previous
#include <cuda_runtime.h>
#include <cuda_bf16.h>
#include <math.h>
#include <stdint.h>

#define NN 512
#define CC 128
#define NPOS (NN*NN)           // 262144 positions

// Scratch planes (channel-major): a[c][pos], b[c][pos], tri[pos-major per plane]
__device__ float g_a[(size_t)CC * NPOS];
__device__ float g_b[(size_t)CC * NPOS];
__device__ float g_t[(size_t)CC * NPOS];

// ---------------------------------------------------------------------------
// helpers
// ---------------------------------------------------------------------------
__device__ __forceinline__ uint32_t f2tf(float x) {
    uint32_t u;
    asm("cvt.rna.tf32.f32 %0, %1;" : "=r"(u) : "f"(x));
    return u;
}
__device__ __forceinline__ float f2tff(float x) { return __uint_as_float(f2tf(x)); }

__device__ __forceinline__ void mma8(float* d, const uint32_t* a, const uint32_t* b) {
    asm volatile(
        "mma.sync.aligned.m16n8k8.row.col.f32.tf32.tf32.f32 "
        "{%0,%1,%2,%3}, {%4,%5,%6,%7}, {%8,%9}, {%0,%1,%2,%3};\n"
        : "+f"(d[0]), "+f"(d[1]), "+f"(d[2]), "+f"(d[3])
        : "r"(a[0]), "r"(a[1]), "r"(a[2]), "r"(a[3]), "r"(b[0]), "r"(b[1]));
}

__device__ __forceinline__ float sigm(float x) {
    return __fdividef(1.f, 1.f + __expf(-x));
}

__device__ __forceinline__ uint32_t ldsu(const float* p) { return __float_as_uint(*p); }

// ---------------------------------------------------------------------------
// Kernel A: LN1 + [128 x 128] @ Wp^T/Wg^T (tf32 MMA) + mask*sigmoid + split
// CTA: 256 thr, 128 positions. smem: xs[128][132], ws[2][64][132], mrow[128]
// pad 132: 132 % 32 == 4 -> fragment LDS conflict-free
// ---------------------------------------------------------------------------
#define XS_PAD 132
#define KA_SMEM ((128*XS_PAD + 2*64*XS_PAD + 128) * sizeof(float))

__global__ void __launch_bounds__(256) kA(const float* __restrict__ pair,
                                          const float* __restrict__ mask,
                                          const float* __restrict__ w1,
                                          const float* __restrict__ b1,
                                          const float* __restrict__ Wp,
                                          const float* __restrict__ Wg)
{
    extern __shared__ float sm[];
    float* xs   = sm;                        // 128*132 (LN'd, tf32-rounded)
    float* ws   = xs + 128*XS_PAD;           // 2 * 64*132
    float* mrow = ws + 2*64*XS_PAD;          // 128

    const int tid = threadIdx.x;
    const int p0  = blockIdx.x * 128;

    // Load 128x128 pair values
    #pragma unroll
    for (int it = 0; it < 64; ++it) {
        int idx = it*256 + tid;              // 0..16383
        int r = idx >> 7, c = idx & 127;
        xs[r*XS_PAD + c] = pair[(size_t)p0*CC + idx];
    }
    if (tid < 128) mrow[tid] = mask[p0 + tid];
    __syncthreads();

    const int warp = tid >> 5, lane = tid & 31;

    // LN1: 8 warps x 16 rows; round result to tf32
    {
        float w1r[4], b1r[4];
        #pragma unroll
        for (int q = 0; q < 4; ++q) { w1r[q] = w1[lane + 32*q]; b1r[q] = b1[lane + 32*q]; }
        for (int rr = 0; rr < 16; ++rr) {
            int r = warp*16 + rr;
            float v[4];
            #pragma unroll
            for (int q = 0; q < 4; ++q) v[q] = xs[r*XS_PAD + lane + 32*q];
            float s = v[0]+v[1]+v[2]+v[3];
            float s2 = v[0]*v[0]+v[1]*v[1]+v[2]*v[2]+v[3]*v[3];
            #pragma unroll
            for (int o = 16; o; o >>= 1) {
                s  += __shfl_xor_sync(0xffffffffu, s , o);
                s2 += __shfl_xor_sync(0xffffffffu, s2, o);
            }
            float mu = s*(1.f/128.f), var = s2*(1.f/128.f) - mu*mu;
            float rstd = rsqrtf(var + 1e-5f);
            #pragma unroll
            for (int q = 0; q < 4; ++q)
                xs[r*XS_PAD + lane + 32*q] = f2tff((v[q]-mu)*rstd*w1r[q] + b1r[q]);
        }
    }
    __syncthreads();

    const int wm = warp >> 1;        // 0..3 -> rows 32*wm
    const int wn = warp & 1;         // 0..1 -> cols 32*wn (within 64-chunk)
    const int gid = lane >> 2, tig = lane & 3;

    for (int o0 = 0; o0 < 256; o0 += 64) {
        // Load weight chunks (tf32-rounded): ws[0][n][k]=Wp, ws[1][n][k]=Wg
        #pragma unroll
        for (int it = 0; it < 32; ++it) {
            int idx = it*256 + tid;          // 0..8191
            int n = idx >> 7, k = idx & 127;
            ws[n*XS_PAD + k]              = f2tff(Wp[(size_t)(o0+n)*CC + k]);
            ws[64*XS_PAD + n*XS_PAD + k]  = f2tff(Wg[(size_t)(o0+n)*CC + k]);
        }
        __syncthreads();

        float accP[2][4][4] = {}, accG[2][4][4] = {};

        #pragma unroll
        for (int k8 = 0; k8 < 128; k8 += 8) {
            uint32_t a[2][4];
            #pragma unroll
            for (int mt = 0; mt < 2; ++mt) {
                int r0 = 32*wm + 16*mt + gid;
                a[mt][0] = ldsu(&xs[r0*XS_PAD + k8 + tig]);
                a[mt][1] = ldsu(&xs[(r0+8)*XS_PAD + k8 + tig]);
                a[mt][2] = ldsu(&xs[r0*XS_PAD + k8 + 4 + tig]);
                a[mt][3] = ldsu(&xs[(r0+8)*XS_PAD + k8 + 4 + tig]);
            }
            uint32_t bp[4][2], bg[4][2];
            #pragma unroll
            for (int nt = 0; nt < 4; ++nt) {
                int n0 = 32*wn + 8*nt + gid;
                bp[nt][0] = ldsu(&ws[n0*XS_PAD + k8 + tig]);
                bp[nt][1] = ldsu(&ws[n0*XS_PAD + k8 + 4 + tig]);
                bg[nt][0] = ldsu(&ws[64*XS_PAD + n0*XS_PAD + k8 + tig]);
                bg[nt][1] = ldsu(&ws[64*XS_PAD + n0*XS_PAD + k8 + 4 + tig]);
            }
            #pragma unroll
            for (int mt = 0; mt < 2; ++mt)
                #pragma unroll
                for (int nt = 0; nt < 4; ++nt) {
                    mma8(accP[mt][nt], a[mt], bp[nt]);
                    mma8(accG[mt][nt], a[mt], bg[nt]);
                }
        }
        __syncthreads();   // ws reused next chunk

        // Epilogue: gate + parity split into channel planes (tf32-rounded)
        #pragma unroll
        for (int mt = 0; mt < 2; ++mt) {
            int rl0 = 32*wm + 16*mt + gid;
            int rl1 = rl0 + 8;
            float m0 = mrow[rl0], m1 = mrow[rl1];
            #pragma unroll
            for (int nt = 0; nt < 4; ++nt) {
                int colE = o0 + 32*wn + 8*nt + 2*tig;  // even
                int q = colE >> 1;
                const float* P = accP[mt][nt];
                const float* G = accG[mt][nt];
                size_t base = (size_t)q*NPOS + p0;
                g_a[base + rl0] = f2tff(P[0] * m0 * sigm(G[0]));
                g_b[base + rl0] = f2tff(P[1] * m0 * sigm(G[1]));
                g_a[base + rl1] = f2tff(P[2] * m1 * sigm(G[2]));
                g_b[base + rl1] = f2tff(P[3] * m1 * sigm(G[3]));
            }
        }
    }
}

// ---------------------------------------------------------------------------
// Kernel B: per-channel NT tf32 GEMM  T_c = A_c @ B_c^T, 512x512x512
// CTA: 256 thr, 128x128 tile, K-step 16, double-buffered.
// smem pad 20 floats/row: 20 % 32 has the property (20*r + c) distinct banks.
// ---------------------------------------------------------------------------
#define KB_PAD 20

__global__ void __launch_bounds__(256) kB()
{
    const int c  = blockIdx.z;
    const float* __restrict__ A = g_a + (size_t)c * NPOS;
    const float* __restrict__ B = g_b + (size_t)c * NPOS;
    float* __restrict__ T = g_t + (size_t)c * NPOS;
    const int i0 = blockIdx.y * 128;
    const int j0 = blockIdx.x * 128;

    __shared__ float As[2][128*KB_PAD];
    __shared__ float Bs[2][128*KB_PAD];

    const int tid = threadIdx.x;
    const int warp = tid >> 5, lane = tid & 31;
    const int wm = warp & 1;         // rows 64*wm
    const int wn = warp >> 1;        // cols 32*wn
    const int gid = lane >> 2, tig = lane & 3;

    float acc[4][4][4] = {};         // [mt][nt][frag]

    // fill buffer 0
    {
        #pragma unroll
        for (int it = 0; it < 2; ++it) {
            int idx = it*256 + tid;          // 0..511
            int row = idx >> 2, q = idx & 3;
            float4 av = *(const float4*)&A[(size_t)(i0+row)*NN + 4*q];
            float4 bv = *(const float4*)&B[(size_t)(j0+row)*NN + 4*q];
            *(float4*)&As[0][row*KB_PAD + 4*q] = av;
            *(float4*)&Bs[0][row*KB_PAD + 4*q] = bv;
        }
    }
    __syncthreads();

    for (int kt = 0; kt < 32; ++kt) {
        const int cur = kt & 1;
        float4 ra[2], rb[2];
        if (kt < 31) {
            int k0 = (kt+1) * 16;
            #pragma unroll
            for (int it = 0; it < 2; ++it) {
                int idx = it*256 + tid;
                int row = idx >> 2, q = idx & 3;
                ra[it] = *(const float4*)&A[(size_t)(i0+row)*NN + k0 + 4*q];
                rb[it] = *(const float4*)&B[(size_t)(j0+row)*NN + k0 + 4*q];
            }
        }

        const float* Ac = As[cur];
        const float* Bc = Bs[cur];
        #pragma unroll
        for (int s = 0; s < 2; ++s) {
            int kc = 8*s + tig;
            uint32_t a[4][4], b[4][2];
            #pragma unroll
            for (int mt = 0; mt < 4; ++mt) {
                int r0 = 64*wm + 16*mt + gid;
                a[mt][0] = ldsu(&Ac[r0*KB_PAD + kc]);
                a[mt][1] = ldsu(&Ac[(r0+8)*KB_PAD + kc]);
                a[mt][2] = ldsu(&Ac[r0*KB_PAD + kc + 4]);
                a[mt][3] = ldsu(&Ac[(r0+8)*KB_PAD + kc + 4]);
            }
            #pragma unroll
            for (int nt = 0; nt < 4; ++nt) {
                int n0 = 32*wn + 8*nt + gid;
                b[nt][0] = ldsu(&Bc[n0*KB_PAD + kc]);
                b[nt][1] = ldsu(&Bc[n0*KB_PAD + kc + 4]);
            }
            #pragma unroll
            for (int mt = 0; mt < 4; ++mt)
                #pragma unroll
                for (int nt = 0; nt < 4; ++nt)
                    mma8(acc[mt][nt], a[mt], b[nt]);
        }

        if (kt < 31) {
            __syncthreads();
            #pragma unroll
            for (int it = 0; it < 2; ++it) {
                int idx = it*256 + tid;
                int row = idx >> 2, q = idx & 3;
                *(float4*)&As[cur^1][row*KB_PAD + 4*q] = ra[it];
                *(float4*)&Bs[cur^1][row*KB_PAD + 4*q] = rb[it];
            }
            __syncthreads();
        }
    }

    // Epilogue: float2 stores
    #pragma unroll
    for (int mt = 0; mt < 4; ++mt) {
        int r0 = i0 + 64*wm + 16*mt + gid;
        #pragma unroll
        for (int nt = 0; nt < 4; ++nt) {
            int cb = j0 + 32*wn + 8*nt + 2*tig;
            float2 v0 = make_float2(acc[mt][nt][0], acc[mt][nt][1]);
            float2 v1 = make_float2(acc[mt][nt][2], acc[mt][nt][3]);
            *(float2*)&T[(size_t)r0*NN + cb]     = v0;
            *(float2*)&T[(size_t)(r0+8)*NN + cb] = v1;
        }
    }
}

// ---------------------------------------------------------------------------
// Kernel C: LN2(tri)@Wo^T * sigmoid(LN1(pair)@Wgl^T) + pair  (tf32 MMA)
// CTA: 256 thr, 128 positions. smem: t_sm[128][132], x_sm[128][132],
// ws[2][64][132]
// ---------------------------------------------------------------------------
#define KC_SMEM ((2*128*XS_PAD + 2*64*XS_PAD) * sizeof(float))

__global__ void __launch_bounds__(256) kC(const float* __restrict__ pair,
                                          const float* __restrict__ w1,
                                          const float* __restrict__ b1,
                                          const float* __restrict__ w2,
                                          const float* __restrict__ b2,
                                          const float* __restrict__ Wo,
                                          const float* __restrict__ Wgl,
                                          float* __restrict__ out)
{
    extern __shared__ float sm[];
    float* t_sm = sm;                        // 128*132
    float* x_sm = t_sm + 128*XS_PAD;         // 128*132
    float* ws   = x_sm + 128*XS_PAD;         // 2 * 64*132

    const int tid = threadIdx.x;
    const int p0  = blockIdx.x * 128;

    // pair tile (row-major)
    #pragma unroll
    for (int it = 0; it < 64; ++it) {
        int idx = it*256 + tid;
        int r = idx >> 7, c = idx & 127;
        x_sm[r*XS_PAD + c] = pair[(size_t)p0*CC + idx];
    }
    // tri tile from plane-major g_t (coalesced over positions)
    #pragma unroll
    for (int it = 0; it < 64; ++it) {
        int idx = it*256 + tid;
        int r = idx & 127, c = idx >> 7;
        t_sm[r*XS_PAD + c] = g_t[(size_t)c*NPOS + p0 + r];
    }
    __syncthreads();

    const int warp = tid >> 5, lane = tid & 31;

    // LN2 on t_sm, LN1 on x_sm, tf32-rounded
    {
        float w1r[4], b1r[4], w2r[4], b2r[4];
        #pragma unroll
        for (int q = 0; q < 4; ++q) {
            w1r[q] = w1[lane + 32*q]; b1r[q] = b1[lane + 32*q];
            w2r[q] = w2[lane + 32*q]; b2r[q] = b2[lane + 32*q];
        }
        for (int rr = 0; rr < 16; ++rr) {
            int r = warp*16 + rr;
            {
                float v[4];
                #pragma unroll
                for (int q = 0; q < 4; ++q) v[q] = t_sm[r*XS_PAD + lane + 32*q];
                float s = v[0]+v[1]+v[2]+v[3];
                float s2 = v[0]*v[0]+v[1]*v[1]+v[2]*v[2]+v[3]*v[3];
                #pragma unroll
                for (int o = 16; o; o >>= 1) {
                    s  += __shfl_xor_sync(0xffffffffu, s , o);
                    s2 += __shfl_xor_sync(0xffffffffu, s2, o);
                }
                float mu = s*(1.f/128.f), var = s2*(1.f/128.f) - mu*mu;
                float rstd = rsqrtf(var + 1e-5f);
                #pragma unroll
                for (int q = 0; q < 4; ++q)
                    t_sm[r*XS_PAD + lane + 32*q] = f2tff((v[q]-mu)*rstd*w2r[q] + b2r[q]);
            }
            {
                float v[4];
                #pragma unroll
                for (int q = 0; q < 4; ++q) v[q] = x_sm[r*XS_PAD + lane + 32*q];
                float s = v[0]+v[1]+v[2]+v[3];
                float s2 = v[0]*v[0]+v[1]*v[1]+v[2]*v[2]+v[3]*v[3];
                #pragma unroll
                for (int o = 16; o; o >>= 1) {
                    s  += __shfl_xor_sync(0xffffffffu, s , o);
                    s2 += __shfl_xor_sync(0xffffffffu, s2, o);
                }
                float mu = s*(1.f/128.f), var = s2*(1.f/128.f) - mu*mu;
                float rstd = rsqrtf(var + 1e-5f);
                #pragma unroll
                for (int q = 0; q < 4; ++q)
                    x_sm[r*XS_PAD + lane + 32*q] = f2tff((v[q]-mu)*rstd*w1r[q] + b1r[q]);
            }
        }
    }
    __syncthreads();

    const int wm = warp >> 1;        // rows 32*wm
    const int wn = warp & 1;         // cols 32*wn within 64-chunk
    const int gid = lane >> 2, tig = lane & 3;

    for (int o0 = 0; o0 < 128; o0 += 64) {
        #pragma unroll
        for (int it = 0; it < 32; ++it) {
            int idx = it*256 + tid;
            int n = idx >> 7, k = idx & 127;
            ws[n*XS_PAD + k]             = f2tff(Wo [(size_t)(o0+n)*CC + k]);
            ws[64*XS_PAD + n*XS_PAD + k] = f2tff(Wgl[(size_t)(o0+n)*CC + k]);
        }
        __syncthreads();

        float accO[2][4][4] = {}, accG[2][4][4] = {};

        #pragma unroll
        for (int k8 = 0; k8 < 128; k8 += 8) {
            uint32_t at[2][4], ax[2][4];
            #pragma unroll
            for (int mt = 0; mt < 2; ++mt) {
                int r0 = 32*wm + 16*mt + gid;
                at[mt][0] = ldsu(&t_sm[r0*XS_PAD + k8 + tig]);
                at[mt][1] = ldsu(&t_sm[(r0+8)*XS_PAD + k8 + tig]);
                at[mt][2] = ldsu(&t_sm[r0*XS_PAD + k8 + 4 + tig]);
                at[mt][3] = ldsu(&t_sm[(r0+8)*XS_PAD + k8 + 4 + tig]);
                ax[mt][0] = ldsu(&x_sm[r0*XS_PAD + k8 + tig]);
                ax[mt][1] = ldsu(&x_sm[(r0+8)*XS_PAD + k8 + tig]);
                ax[mt][2] = ldsu(&x_sm[r0*XS_PAD + k8 + 4 + tig]);
                ax[mt][3] = ldsu(&x_sm[(r0+8)*XS_PAD + k8 + 4 + tig]);
            }
            uint32_t bo[4][2], bg[4][2];
            #pragma unroll
            for (int nt = 0; nt < 4; ++nt) {
                int n0 = 32*wn + 8*nt + gid;
                bo[nt][0] = ldsu(&ws[n0*XS_PAD + k8 + tig]);
                bo[nt][1] = ldsu(&ws[n0*XS_PAD + k8 + 4 + tig]);
                bg[nt][0] = ldsu(&ws[64*XS_PAD + n0*XS_PAD + k8 + tig]);
                bg[nt][1] = ldsu(&ws[64*XS_PAD + n0*XS_PAD + k8 + 4 + tig]);
            }
            #pragma unroll
            for (int mt = 0; mt < 2; ++mt)
                #pragma unroll
                for (int nt = 0; nt < 4; ++nt) {
                    mma8(accO[mt][nt], at[mt], bo[nt]);
                    mma8(accG[mt][nt], ax[mt], bg[nt]);
                }
        }
        __syncthreads();

        // Epilogue: out = pair + O * sigmoid(G), float2 stores
        #pragma unroll
        for (int mt = 0; mt < 2; ++mt) {
            int rl0 = 32*wm + 16*mt + gid;
            #pragma unroll
            for (int nt = 0; nt < 4; ++nt) {
                int col = o0 + 32*wn + 8*nt + 2*tig;
                const float* O = accO[mt][nt];
                const float* G = accG[mt][nt];
                {
                    size_t a0 = (size_t)(p0 + rl0)*CC + col;
                    float2 pr = *(const float2*)&pair[a0];
                    float2 ov;
                    ov.x = pr.x + O[0] * sigm(G[0]);
                    ov.y = pr.y + O[1] * sigm(G[1]);
                    *(float2*)&out[a0] = ov;
                }
                {
                    size_t a1 = (size_t)(p0 + rl0 + 8)*CC + col;
                    float2 pr = *(const float2*)&pair[a1];
                    float2 ov;
                    ov.x = pr.x + O[2] * sigm(G[2]);
                    ov.y = pr.y + O[3] * sigm(G[3]);
                    *(float2*)&out[a1] = ov;
                }
            }
        }
    }
}

// ---------------------------------------------------------------------------
extern "C" void kernel_launch(void* const* d_in, const int* in_sizes, int n_in,
                              void* d_out, int out_size)
{
    const float* pair = (const float*)d_in[0];
    const float* mask = (const float*)d_in[1];
    const float* w1   = (const float*)d_in[2];
    const float* b1   = (const float*)d_in[3];
    const float* Wp   = (const float*)d_in[4];
    const float* Wg   = (const float*)d_in[5];
    const float* w2   = (const float*)d_in[6];
    const float* b2   = (const float*)d_in[7];
    const float* Wo   = (const float*)d_in[8];
    const float* Wgl  = (const float*)d_in[9];
    float* out = (float*)d_out;

    cudaFuncSetAttribute(kA, cudaFuncAttributeMaxDynamicSharedMemorySize, (int)KA_SMEM);
    cudaFuncSetAttribute(kC, cudaFuncAttributeMaxDynamicSharedMemorySize, (int)KC_SMEM);

    kA<<<NPOS/128, 256, KA_SMEM>>>(pair, mask, w1, b1, Wp, Wg);
    kB<<<dim3(NN/128, NN/128, CC), 256>>>();
    kC<<<NPOS/128, 256, KC_SMEM>>>(pair, w1, b1, w2, b2, Wo, Wgl, out);
}

// round 4
// speedup vs baseline: 3.0640x; 1.0483x over previous
#include <cuda_runtime.h>
#include <cuda_bf16.h>
#include <math.h>
#include <stdint.h>

#define NN 512
#define CC 128
#define NPOS (NN*NN)

__device__ float g_a[(size_t)CC * NPOS];
__device__ float g_b[(size_t)CC * NPOS];
__device__ float g_t[(size_t)CC * NPOS];

// ---------------------------------------------------------------------------
// helpers
// ---------------------------------------------------------------------------
__device__ __forceinline__ uint32_t f2tf(float x) {
    uint32_t u;
    asm("cvt.rna.tf32.f32 %0, %1;" : "=r"(u) : "f"(x));
    return u;
}
__device__ __forceinline__ float f2tff(float x) { return __uint_as_float(f2tf(x)); }

__device__ __forceinline__ void mma8(float* d, const uint32_t* a, const uint32_t* b) {
    asm volatile(
        "mma.sync.aligned.m16n8k8.row.col.f32.tf32.tf32.f32 "
        "{%0,%1,%2,%3}, {%4,%5,%6,%7}, {%8,%9}, {%0,%1,%2,%3};\n"
        : "+f"(d[0]), "+f"(d[1]), "+f"(d[2]), "+f"(d[3])
        : "r"(a[0]), "r"(a[1]), "r"(a[2]), "r"(a[3]), "r"(b[0]), "r"(b[1]));
}

__device__ __forceinline__ float sigm(float x) {
    return __fdividef(1.f, 1.f + __expf(-x));
}
__device__ __forceinline__ uint32_t ldsu(const float* p) { return __float_as_uint(*p); }

__device__ __forceinline__ void cpa16(uint32_t dst, const void* src) {
    asm volatile("cp.async.cg.shared.global [%0], [%1], 16;" :: "r"(dst), "l"(src));
}

// ---------------------------------------------------------------------------
// Kernel A: LN1 + [128pos x 256out] tf32 MMA vs Wp/Wg + mask*sigmoid + split
// CTA: 512 threads (16 warps), 128 positions, 4 chunks of 64 outputs.
// smem: xs[128][132], ws[2][64][132] (wp half reused as coalescing stage), mrow
// ---------------------------------------------------------------------------
#define XS_PAD 132
#define KA_SMEM ((128*XS_PAD + 2*64*XS_PAD + 128) * sizeof(float))

__global__ void __launch_bounds__(512) kA(const float* __restrict__ pair,
                                          const float* __restrict__ mask,
                                          const float* __restrict__ w1,
                                          const float* __restrict__ b1,
                                          const float* __restrict__ Wp,
                                          const float* __restrict__ Wg)
{
    extern __shared__ float sm[];
    float* xs   = sm;                        // 128*132
    float* ws   = xs + 128*XS_PAD;           // 2 * 64*132 (wp | wg)
    float* mrow = ws + 2*64*XS_PAD;          // 128

    const int tid = threadIdx.x;
    const int p0  = blockIdx.x * 128;

    #pragma unroll
    for (int it = 0; it < 32; ++it) {
        int idx = it*512 + tid;              // 0..16383
        int r = idx >> 7, c = idx & 127;
        xs[r*XS_PAD + c] = pair[(size_t)p0*CC + idx];
    }
    if (tid < 128) mrow[tid] = mask[p0 + tid];
    __syncthreads();

    const int warp = tid >> 5, lane = tid & 31;

    // LN1: 16 warps x 8 rows; round to tf32
    {
        float w1r[4], b1r[4];
        #pragma unroll
        for (int q = 0; q < 4; ++q) { w1r[q] = w1[lane + 32*q]; b1r[q] = b1[lane + 32*q]; }
        #pragma unroll
        for (int rr = 0; rr < 8; ++rr) {
            int r = warp*8 + rr;
            float v[4];
            #pragma unroll
            for (int q = 0; q < 4; ++q) v[q] = xs[r*XS_PAD + lane + 32*q];
            float s = v[0]+v[1]+v[2]+v[3];
            float s2 = v[0]*v[0]+v[1]*v[1]+v[2]*v[2]+v[3]*v[3];
            #pragma unroll
            for (int o = 16; o; o >>= 1) {
                s  += __shfl_xor_sync(0xffffffffu, s , o);
                s2 += __shfl_xor_sync(0xffffffffu, s2, o);
            }
            float mu = s*(1.f/128.f), var = s2*(1.f/128.f) - mu*mu;
            float rstd = rsqrtf(var + 1e-5f);
            #pragma unroll
            for (int q = 0; q < 4; ++q)
                xs[r*XS_PAD + lane + 32*q] = f2tff((v[q]-mu)*rstd*w1r[q] + b1r[q]);
        }
    }
    __syncthreads();

    // warp grid: wm in 0..3 -> rows 32*wm (2 m16 tiles), wn in 0..3 -> cols 16*wn
    const int wm = warp & 3;
    const int wn = warp >> 2;
    const int gid = lane >> 2, tig = lane & 3;

    for (int o0 = 0; o0 < 256; o0 += 64) {
        // load weight chunk (tf32-rounded): ws[n][k]=Wp, ws[64..][k]=Wg
        #pragma unroll
        for (int it = 0; it < 16; ++it) {
            int idx = it*512 + tid;          // 0..8191
            int n = idx >> 7, k = idx & 127;
            ws[n*XS_PAD + k]             = f2tff(Wp[(size_t)(o0+n)*CC + k]);
            ws[64*XS_PAD + n*XS_PAD + k] = f2tff(Wg[(size_t)(o0+n)*CC + k]);
        }
        __syncthreads();

        float accP[2][2][4] = {}, accG[2][2][4] = {};

        #pragma unroll
        for (int k8 = 0; k8 < 128; k8 += 8) {
            uint32_t a[2][4];
            #pragma unroll
            for (int mt = 0; mt < 2; ++mt) {
                int r0 = 32*wm + 16*mt + gid;
                a[mt][0] = ldsu(&xs[r0*XS_PAD + k8 + tig]);
                a[mt][1] = ldsu(&xs[(r0+8)*XS_PAD + k8 + tig]);
                a[mt][2] = ldsu(&xs[r0*XS_PAD + k8 + 4 + tig]);
                a[mt][3] = ldsu(&xs[(r0+8)*XS_PAD + k8 + 4 + tig]);
            }
            uint32_t bp[2][2], bg[2][2];
            #pragma unroll
            for (int nt = 0; nt < 2; ++nt) {
                int n0 = 16*wn + 8*nt + gid;
                bp[nt][0] = ldsu(&ws[n0*XS_PAD + k8 + tig]);
                bp[nt][1] = ldsu(&ws[n0*XS_PAD + k8 + 4 + tig]);
                bg[nt][0] = ldsu(&ws[64*XS_PAD + n0*XS_PAD + k8 + tig]);
                bg[nt][1] = ldsu(&ws[64*XS_PAD + n0*XS_PAD + k8 + 4 + tig]);
            }
            #pragma unroll
            for (int mt = 0; mt < 2; ++mt)
                #pragma unroll
                for (int nt = 0; nt < 2; ++nt) {
                    mma8(accP[mt][nt], a[mt], bp[nt]);
                    mma8(accG[mt][nt], a[mt], bg[nt]);
                }
        }
        __syncthreads();     // done reading ws -> reuse wp half as stage

        // stage gated results [col][row], tf32-rounded
        float* stage = ws;   // 64*132 floats
        #pragma unroll
        for (int mt = 0; mt < 2; ++mt) {
            int rl0 = 32*wm + 16*mt + gid;
            int rl1 = rl0 + 8;
            float m0 = mrow[rl0], m1 = mrow[rl1];
            #pragma unroll
            for (int nt = 0; nt < 2; ++nt) {
                int cl = 16*wn + 8*nt + 2*tig;
                const float* P = accP[mt][nt];
                const float* G = accG[mt][nt];
                stage[cl*XS_PAD + rl0]     = f2tff(P[0] * m0 * sigm(G[0]));
                stage[(cl+1)*XS_PAD + rl0] = f2tff(P[1] * m0 * sigm(G[1]));
                stage[cl*XS_PAD + rl1]     = f2tff(P[2] * m1 * sigm(G[2]));
                stage[(cl+1)*XS_PAD + rl1] = f2tff(P[3] * m1 * sigm(G[3]));
            }
        }
        __syncthreads();

        // coalesced copy: 64 segments x 128 contiguous floats
        #pragma unroll
        for (int it = 0; it < 16; ++it) {
            int idx = it*512 + tid;          // 0..8191
            int seg = idx >> 7, r = idx & 127;
            int og = o0 + seg;
            float* dst = (og & 1) ? g_b : g_a;
            dst[(size_t)(og >> 1)*NPOS + p0 + r] = stage[seg*XS_PAD + r];
        }
        __syncthreads();
    }
}

// ---------------------------------------------------------------------------
// Kernel B: per-channel NT tf32 GEMM  T_c = A_c @ B_c^T, 512x512x512
// CTA: 256 thr (2 CTAs/SM), 128x128 tile, K-step 16, cp.async double buffer.
// ---------------------------------------------------------------------------
#define KB_PAD 20

__global__ void __launch_bounds__(256, 2) kB()
{
    const int c  = blockIdx.z;
    const float* __restrict__ A = g_a + (size_t)c * NPOS;
    const float* __restrict__ B = g_b + (size_t)c * NPOS;
    float* __restrict__ T = g_t + (size_t)c * NPOS;
    const int i0 = blockIdx.y * 128;
    const int j0 = blockIdx.x * 128;

    __shared__ float As[2][128*KB_PAD];
    __shared__ float Bs[2][128*KB_PAD];
    const uint32_t sA = (uint32_t)__cvta_generic_to_shared(&As[0][0]);
    const uint32_t sB = (uint32_t)__cvta_generic_to_shared(&Bs[0][0]);

    const int tid = threadIdx.x;
    const int warp = tid >> 5, lane = tid & 31;
    const int wm = warp & 1;
    const int wn = warp >> 1;
    const int gid = lane >> 2, tig = lane & 3;

    const int lrow = tid >> 2;              // 0..63 base row pattern (2 iters)
    const int lq   = (tid & 3) * 4;         // 0,4,8,12

    float acc[4][4][4] = {};

    // prefetch tile 0
    #pragma unroll
    for (int it = 0; it < 2; ++it) {
        int row = it*64 + lrow;
        cpa16(sA + (uint32_t)((row*KB_PAD + lq) * 4), &A[(size_t)(i0+row)*NN + lq]);
        cpa16(sB + (uint32_t)((row*KB_PAD + lq) * 4), &B[(size_t)(j0+row)*NN + lq]);
    }
    asm volatile("cp.async.commit_group;");

    for (int kt = 0; kt < 32; ++kt) {
        const int cur = kt & 1;
        if (kt < 31) {
            const int nxt = cur ^ 1;
            const int k0 = (kt+1) * 16;
            const uint32_t boff = (uint32_t)(nxt * 128*KB_PAD * 4);
            #pragma unroll
            for (int it = 0; it < 2; ++it) {
                int row = it*64 + lrow;
                cpa16(sA + boff + (uint32_t)((row*KB_PAD + lq) * 4),
                      &A[(size_t)(i0+row)*NN + k0 + lq]);
                cpa16(sB + boff + (uint32_t)((row*KB_PAD + lq) * 4),
                      &B[(size_t)(j0+row)*NN + k0 + lq]);
            }
            asm volatile("cp.async.commit_group;");
            asm volatile("cp.async.wait_group 1;");
        } else {
            asm volatile("cp.async.wait_group 0;");
        }
        __syncthreads();

        const float* Ac = As[cur];
        const float* Bc = Bs[cur];
        #pragma unroll
        for (int s = 0; s < 2; ++s) {
            int kc = 8*s + tig;
            uint32_t a[4][4], b[4][2];
            #pragma unroll
            for (int mt = 0; mt < 4; ++mt) {
                int r0 = 64*wm + 16*mt + gid;
                a[mt][0] = ldsu(&Ac[r0*KB_PAD + kc]);
                a[mt][1] = ldsu(&Ac[(r0+8)*KB_PAD + kc]);
                a[mt][2] = ldsu(&Ac[r0*KB_PAD + kc + 4]);
                a[mt][3] = ldsu(&Ac[(r0+8)*KB_PAD + kc + 4]);
            }
            #pragma unroll
            for (int nt = 0; nt < 4; ++nt) {
                int n0 = 32*wn + 8*nt + gid;
                b[nt][0] = ldsu(&Bc[n0*KB_PAD + kc]);
                b[nt][1] = ldsu(&Bc[n0*KB_PAD + kc + 4]);
            }
            #pragma unroll
            for (int mt = 0; mt < 4; ++mt)
                #pragma unroll
                for (int nt = 0; nt < 4; ++nt)
                    mma8(acc[mt][nt], a[mt], b[nt]);
        }
        __syncthreads();
    }

    #pragma unroll
    for (int mt = 0; mt < 4; ++mt) {
        int r0 = i0 + 64*wm + 16*mt + gid;
        #pragma unroll
        for (int nt = 0; nt < 4; ++nt) {
            int cb = j0 + 32*wn + 8*nt + 2*tig;
            *(float2*)&T[(size_t)r0*NN + cb]     = make_float2(acc[mt][nt][0], acc[mt][nt][1]);
            *(float2*)&T[(size_t)(r0+8)*NN + cb] = make_float2(acc[mt][nt][2], acc[mt][nt][3]);
        }
    }
}

// ---------------------------------------------------------------------------
// Kernel C: LN2(tri)@Wo^T * sigmoid(LN1(pair)@Wgl^T) + pair
// CTA: 512 threads (16 warps), 128 positions, 2 chunks of 64 outputs.
// ---------------------------------------------------------------------------
#define KC_SMEM ((2*128*XS_PAD + 2*64*XS_PAD) * sizeof(float))

__global__ void __launch_bounds__(512) kC(const float* __restrict__ pair,
                                          const float* __restrict__ w1,
                                          const float* __restrict__ b1,
                                          const float* __restrict__ w2,
                                          const float* __restrict__ b2,
                                          const float* __restrict__ Wo,
                                          const float* __restrict__ Wgl,
                                          float* __restrict__ out)
{
    extern __shared__ float sm[];
    float* t_sm = sm;                        // 128*132
    float* x_sm = t_sm + 128*XS_PAD;         // 128*132
    float* ws   = x_sm + 128*XS_PAD;         // 2 * 64*132

    const int tid = threadIdx.x;
    const int p0  = blockIdx.x * 128;

    #pragma unroll
    for (int it = 0; it < 32; ++it) {
        int idx = it*512 + tid;
        int r = idx >> 7, c = idx & 127;
        x_sm[r*XS_PAD + c] = pair[(size_t)p0*CC + idx];
    }
    #pragma unroll
    for (int it = 0; it < 32; ++it) {
        int idx = it*512 + tid;
        int r = idx & 127, c = idx >> 7;
        t_sm[r*XS_PAD + c] = g_t[(size_t)c*NPOS + p0 + r];
    }
    __syncthreads();

    const int warp = tid >> 5, lane = tid & 31;

    // LN2 on t_sm, LN1 on x_sm: 16 warps x 8 rows
    {
        float w1r[4], b1r[4], w2r[4], b2r[4];
        #pragma unroll
        for (int q = 0; q < 4; ++q) {
            w1r[q] = w1[lane + 32*q]; b1r[q] = b1[lane + 32*q];
            w2r[q] = w2[lane + 32*q]; b2r[q] = b2[lane + 32*q];
        }
        #pragma unroll
        for (int rr = 0; rr < 8; ++rr) {
            int r = warp*8 + rr;
            {
                float v[4];
                #pragma unroll
                for (int q = 0; q < 4; ++q) v[q] = t_sm[r*XS_PAD + lane + 32*q];
                float s = v[0]+v[1]+v[2]+v[3];
                float s2 = v[0]*v[0]+v[1]*v[1]+v[2]*v[2]+v[3]*v[3];
                #pragma unroll
                for (int o = 16; o; o >>= 1) {
                    s  += __shfl_xor_sync(0xffffffffu, s , o);
                    s2 += __shfl_xor_sync(0xffffffffu, s2, o);
                }
                float mu = s*(1.f/128.f), var = s2*(1.f/128.f) - mu*mu;
                float rstd = rsqrtf(var + 1e-5f);
                #pragma unroll
                for (int q = 0; q < 4; ++q)
                    t_sm[r*XS_PAD + lane + 32*q] = f2tff((v[q]-mu)*rstd*w2r[q] + b2r[q]);
            }
            {
                float v[4];
                #pragma unroll
                for (int q = 0; q < 4; ++q) v[q] = x_sm[r*XS_PAD + lane + 32*q];
                float s = v[0]+v[1]+v[2]+v[3];
                float s2 = v[0]*v[0]+v[1]*v[1]+v[2]*v[2]+v[3]*v[3];
                #pragma unroll
                for (int o = 16; o; o >>= 1) {
                    s  += __shfl_xor_sync(0xffffffffu, s , o);
                    s2 += __shfl_xor_sync(0xffffffffu, s2, o);
                }
                float mu = s*(1.f/128.f), var = s2*(1.f/128.f) - mu*mu;
                float rstd = rsqrtf(var + 1e-5f);
                #pragma unroll
                for (int q = 0; q < 4; ++q)
                    x_sm[r*XS_PAD + lane + 32*q] = f2tff((v[q]-mu)*rstd*w1r[q] + b1r[q]);
            }
        }
    }
    __syncthreads();

    const int wm = warp & 3;
    const int wn = warp >> 2;
    const int gid = lane >> 2, tig = lane & 3;

    for (int o0 = 0; o0 < 128; o0 += 64) {
        #pragma unroll
        for (int it = 0; it < 16; ++it) {
            int idx = it*512 + tid;
            int n = idx >> 7, k = idx & 127;
            ws[n*XS_PAD + k]             = f2tff(Wo [(size_t)(o0+n)*CC + k]);
            ws[64*XS_PAD + n*XS_PAD + k] = f2tff(Wgl[(size_t)(o0+n)*CC + k]);
        }
        __syncthreads();

        float accO[2][2][4] = {}, accG[2][2][4] = {};

        #pragma unroll
        for (int k8 = 0; k8 < 128; k8 += 8) {
            uint32_t at[2][4], ax[2][4];
            #pragma unroll
            for (int mt = 0; mt < 2; ++mt) {
                int r0 = 32*wm + 16*mt + gid;
                at[mt][0] = ldsu(&t_sm[r0*XS_PAD + k8 + tig]);
                at[mt][1] = ldsu(&t_sm[(r0+8)*XS_PAD + k8 + tig]);
                at[mt][2] = ldsu(&t_sm[r0*XS_PAD + k8 + 4 + tig]);
                at[mt][3] = ldsu(&t_sm[(r0+8)*XS_PAD + k8 + 4 + tig]);
                ax[mt][0] = ldsu(&x_sm[r0*XS_PAD + k8 + tig]);
                ax[mt][1] = ldsu(&x_sm[(r0+8)*XS_PAD + k8 + tig]);
                ax[mt][2] = ldsu(&x_sm[r0*XS_PAD + k8 + 4 + tig]);
                ax[mt][3] = ldsu(&x_sm[(r0+8)*XS_PAD + k8 + 4 + tig]);
            }
            uint32_t bo[2][2], bg[2][2];
            #pragma unroll
            for (int nt = 0; nt < 2; ++nt) {
                int n0 = 16*wn + 8*nt + gid;
                bo[nt][0] = ldsu(&ws[n0*XS_PAD + k8 + tig]);
                bo[nt][1] = ldsu(&ws[n0*XS_PAD + k8 + 4 + tig]);
                bg[nt][0] = ldsu(&ws[64*XS_PAD + n0*XS_PAD + k8 + tig]);
                bg[nt][1] = ldsu(&ws[64*XS_PAD + n0*XS_PAD + k8 + 4 + tig]);
            }
            #pragma unroll
            for (int mt = 0; mt < 2; ++mt)
                #pragma unroll
                for (int nt = 0; nt < 2; ++nt) {
                    mma8(accO[mt][nt], at[mt], bo[nt]);
                    mma8(accG[mt][nt], ax[mt], bg[nt]);
                }
        }
        __syncthreads();

        #pragma unroll
        for (int mt = 0; mt < 2; ++mt) {
            int rl0 = 32*wm + 16*mt + gid;
            #pragma unroll
            for (int nt = 0; nt < 2; ++nt) {
                int col = o0 + 16*wn + 8*nt + 2*tig;
                const float* O = accO[mt][nt];
                const float* G = accG[mt][nt];
                {
                    size_t a0 = (size_t)(p0 + rl0)*CC + col;
                    float2 pr = *(const float2*)&pair[a0];
                    float2 ov;
                    ov.x = pr.x + O[0] * sigm(G[0]);
                    ov.y = pr.y + O[1] * sigm(G[1]);
                    *(float2*)&out[a0] = ov;
                }
                {
                    size_t a1 = (size_t)(p0 + rl0 + 8)*CC + col;
                    float2 pr = *(const float2*)&pair[a1];
                    float2 ov;
                    ov.x = pr.x + O[2] * sigm(G[2]);
                    ov.y = pr.y + O[3] * sigm(G[3]);
                    *(float2*)&out[a1] = ov;
                }
            }
        }
    }
}

// ---------------------------------------------------------------------------
extern "C" void kernel_launch(void* const* d_in, const int* in_sizes, int n_in,
                              void* d_out, int out_size)
{
    const float* pair = (const float*)d_in[0];
    const float* mask = (const float*)d_in[1];
    const float* w1   = (const float*)d_in[2];
    const float* b1   = (const float*)d_in[3];
    const float* Wp   = (const float*)d_in[4];
    const float* Wg   = (const float*)d_in[5];
    const float* w2   = (const float*)d_in[6];
    const float* b2   = (const float*)d_in[7];
    const float* Wo   = (const float*)d_in[8];
    const float* Wgl  = (const float*)d_in[9];
    float* out = (float*)d_out;

    cudaFuncSetAttribute(kA, cudaFuncAttributeMaxDynamicSharedMemorySize, (int)KA_SMEM);
    cudaFuncSetAttribute(kC, cudaFuncAttributeMaxDynamicSharedMemorySize, (int)KC_SMEM);

    kA<<<NPOS/128, 512, KA_SMEM>>>(pair, mask, w1, b1, Wp, Wg);
    kB<<<dim3(NN/128, NN/128, CC), 256>>>();
    kC<<<NPOS/128, 512, KC_SMEM>>>(pair, w1, b1, w2, b2, Wo, Wgl, out);
}

// round 6
// speedup vs baseline: 4.8027x; 1.5675x over previous
#include <cuda_runtime.h>
#include <cuda_fp16.h>
#include <math.h>
#include <stdint.h>

#define NN 512
#define CC 128
#define NPOS (NN*NN)

// Scratch: a/b planes in fp16 (channel-major), tri in fp32
__device__ __half g_a[(size_t)CC * NPOS];
__device__ __half g_b[(size_t)CC * NPOS];
__device__ float  g_t[(size_t)CC * NPOS];

// ---------------------------------------------------------------------------
// helpers
// ---------------------------------------------------------------------------
__device__ __forceinline__ void mma16(float* d, const uint32_t* a, const uint32_t* b) {
    asm volatile(
        "mma.sync.aligned.m16n8k16.row.col.f32.f16.f16.f32 "
        "{%0,%1,%2,%3}, {%4,%5,%6,%7}, {%8,%9}, {%0,%1,%2,%3};\n"
        : "+f"(d[0]), "+f"(d[1]), "+f"(d[2]), "+f"(d[3])
        : "r"(a[0]), "r"(a[1]), "r"(a[2]), "r"(a[3]), "r"(b[0]), "r"(b[1]));
}
__device__ __forceinline__ float sigm(float x) {
    return __fdividef(1.f, 1.f + __expf(-x));
}
__device__ __forceinline__ uint32_t ldh32(const __half* p) {
    return *(const uint32_t*)p;
}
__device__ __forceinline__ void cpa16(uint32_t dst, const void* src) {
    asm volatile("cp.async.cg.shared.global [%0], [%1], 16;" :: "r"(dst), "l"(src));
}

// half-pad 136: fragment LDS banks = gid*68 + tig (mod 32) -> all distinct
#define HP 136

// ---------------------------------------------------------------------------
// Kernel A: LN1 (direct from gmem) + fp16 MMA vs Wp/Wg + mask*sigmoid + split
// CTA: 512 threads, 128 positions. smem (halves/floats):
//   xh[128*HP] half, wh[2*64*HP] half (reused as epilogue stage), mrow[128] f32
// ---------------------------------------------------------------------------
#define KA_SMEM ((128*HP + 2*64*HP) * 2 + 128*4 + 16)

__global__ void __launch_bounds__(512) kA(const float* __restrict__ pair,
                                          const float* __restrict__ mask,
                                          const float* __restrict__ w1,
                                          const float* __restrict__ b1,
                                          const float* __restrict__ Wp,
                                          const float* __restrict__ Wg)
{
    extern __shared__ char smraw[];
    __half* xh  = (__half*)smraw;                 // 128*HP
    __half* wh  = xh + 128*HP;                    // 2 * 64*HP
    float* mrow = (float*)(wh + 2*64*HP);         // 128

    const int tid = threadIdx.x;
    const int p0  = blockIdx.x * 128;
    const int warp = tid >> 5, lane = tid & 31;

    if (tid < 128) mrow[tid] = mask[p0 + tid];

    // LN1 straight from global: 16 warps x 8 rows, float4 per lane
    {
        float4 wv = *(const float4*)&w1[4*lane];
        float4 bv = *(const float4*)&b1[4*lane];
        #pragma unroll
        for (int rr = 0; rr < 8; ++rr) {
            int r = warp*8 + rr;
            float4 v = *(const float4*)&pair[(size_t)(p0 + r)*CC + 4*lane];
            float s  = v.x+v.y+v.z+v.w;
            float s2 = v.x*v.x+v.y*v.y+v.z*v.z+v.w*v.w;
            #pragma unroll
            for (int o = 16; o; o >>= 1) {
                s  += __shfl_xor_sync(0xffffffffu, s , o);
                s2 += __shfl_xor_sync(0xffffffffu, s2, o);
            }
            float mu = s*(1.f/128.f), var = s2*(1.f/128.f) - mu*mu;
            float rstd = rsqrtf(var + 1e-5f);
            float o0 = (v.x-mu)*rstd*wv.x + bv.x;
            float o1 = (v.y-mu)*rstd*wv.y + bv.y;
            float o2 = (v.z-mu)*rstd*wv.z + bv.z;
            float o3 = (v.w-mu)*rstd*wv.w + bv.w;
            *(__half2*)&xh[r*HP + 4*lane]     = __floats2half2_rn(o0, o1);
            *(__half2*)&xh[r*HP + 4*lane + 2] = __floats2half2_rn(o2, o3);
        }
    }
    __syncthreads();

    const int wm = warp & 3;         // rows 32*wm
    const int wn = warp >> 2;        // cols 16*wn within 64-chunk
    const int gid = lane >> 2, tig = lane & 3;

    for (int o0 = 0; o0 < 256; o0 += 64) {
        // weight chunk -> fp16 smem: wh[n][k] (Wp), wh[64*HP + ...] (Wg)
        #pragma unroll
        for (int it = 0; it < 16; ++it) {
            int idx = it*512 + tid;              // 0..8191
            int n = idx >> 7, k = idx & 127;
            wh[n*HP + k]          = __float2half_rn(Wp[(size_t)(o0+n)*CC + k]);
            wh[64*HP + n*HP + k]  = __float2half_rn(Wg[(size_t)(o0+n)*CC + k]);
        }
        __syncthreads();

        float accP[2][2][4] = {}, accG[2][2][4] = {};

        #pragma unroll
        for (int kk = 0; kk < 128; kk += 16) {
            uint32_t a[2][4];
            #pragma unroll
            for (int mt = 0; mt < 2; ++mt) {
                int r0 = 32*wm + 16*mt + gid;
                const __half* base0 = &xh[r0*HP + kk + 2*tig];
                const __half* base1 = &xh[(r0+8)*HP + kk + 2*tig];
                a[mt][0] = ldh32(base0);
                a[mt][1] = ldh32(base1);
                a[mt][2] = ldh32(base0 + 8);
                a[mt][3] = ldh32(base1 + 8);
            }
            uint32_t bp[2][2], bg[2][2];
            #pragma unroll
            for (int nt = 0; nt < 2; ++nt) {
                int n0 = 16*wn + 8*nt + gid;
                const __half* pb = &wh[n0*HP + kk + 2*tig];
                const __half* gb = &wh[64*HP + n0*HP + kk + 2*tig];
                bp[nt][0] = ldh32(pb);  bp[nt][1] = ldh32(pb + 8);
                bg[nt][0] = ldh32(gb);  bg[nt][1] = ldh32(gb + 8);
            }
            #pragma unroll
            for (int mt = 0; mt < 2; ++mt)
                #pragma unroll
                for (int nt = 0; nt < 2; ++nt) {
                    mma16(accP[mt][nt], a[mt], bp[nt]);
                    mma16(accG[mt][nt], a[mt], bg[nt]);
                }
        }
        __syncthreads();     // done with wh -> reuse as stage

        // stage gated fp16 results [col][row]
        __half* stage = wh;  // 64*HP halves
        #pragma unroll
        for (int mt = 0; mt < 2; ++mt) {
            int rl0 = 32*wm + 16*mt + gid;
            int rl1 = rl0 + 8;
            float m0 = mrow[rl0], m1 = mrow[rl1];
            #pragma unroll
            for (int nt = 0; nt < 2; ++nt) {
                int cl = 16*wn + 8*nt + 2*tig;
                const float* P = accP[mt][nt];
                const float* G = accG[mt][nt];
                stage[cl*HP + rl0]     = __float2half_rn(P[0] * m0 * sigm(G[0]));
                stage[(cl+1)*HP + rl0] = __float2half_rn(P[1] * m0 * sigm(G[1]));
                stage[cl*HP + rl1]     = __float2half_rn(P[2] * m1 * sigm(G[2]));
                stage[(cl+1)*HP + rl1] = __float2half_rn(P[3] * m1 * sigm(G[3]));
            }
        }
        __syncthreads();

        // coalesced copy: 64 segments x 128 halves (as 64 u32 words each)
        #pragma unroll
        for (int it = 0; it < 8; ++it) {
            int w = it*512 + tid;                // 0..4095
            int seg = w >> 6, rw = w & 63;
            int og = o0 + seg;
            uint32_t val = *(const uint32_t*)&stage[seg*HP + 2*rw];
            __half* dst = (og & 1) ? g_b : g_a;
            *(uint32_t*)&dst[(size_t)(og >> 1)*NPOS + p0 + 2*rw] = val;
        }
        __syncthreads();
    }
}

// ---------------------------------------------------------------------------
// Kernel B: per-channel NT fp16 GEMM  T_c = A_c @ B_c^T (fp32 accum)
// CTA: 256 thr, 128x128 tile, K-chunk 32 halves, cp.async double buffer.
// smem rows padded to 40 halves (80B, 16B-aligned chunks, conflict-free frags)
// ---------------------------------------------------------------------------
#define KBP 40

__global__ void __launch_bounds__(256, 2) kB()
{
    const int c  = blockIdx.z;
    const __half* __restrict__ A = g_a + (size_t)c * NPOS;
    const __half* __restrict__ B = g_b + (size_t)c * NPOS;
    float* __restrict__ T = g_t + (size_t)c * NPOS;
    const int i0 = blockIdx.y * 128;
    const int j0 = blockIdx.x * 128;

    __shared__ __half As[2][128*KBP];
    __shared__ __half Bs[2][128*KBP];
    const uint32_t sA = (uint32_t)__cvta_generic_to_shared(&As[0][0]);
    const uint32_t sB = (uint32_t)__cvta_generic_to_shared(&Bs[0][0]);

    const int tid = threadIdx.x;
    const int warp = tid >> 5, lane = tid & 31;
    const int wm = warp & 1;
    const int wn = warp >> 1;
    const int gid = lane >> 2, tig = lane & 3;

    float acc[4][4][4] = {};

    // loader: 128 rows x 32 halves (64B/row = 4 x 16B chunks)
    auto load_chunk = [&](int buf, int k0) {
        const uint32_t boff = (uint32_t)(buf * 128*KBP * 2);
        #pragma unroll
        for (int it = 0; it < 2; ++it) {
            int idx = it*256 + tid;              // 0..511
            int row = idx >> 2, g = idx & 3;
            uint32_t doff = (uint32_t)(row*KBP*2 + g*16);
            cpa16(sA + boff + doff, &A[(size_t)(i0+row)*NN + k0 + g*8]);
            cpa16(sB + boff + doff, &B[(size_t)(j0+row)*NN + k0 + g*8]);
        }
        asm volatile("cp.async.commit_group;");
    };

    load_chunk(0, 0);
    load_chunk(1, 32);

    #pragma unroll 1
    for (int kt = 0; kt < 16; ++kt) {
        const int cur = kt & 1;
        if (kt < 15) asm volatile("cp.async.wait_group 1;");
        else         asm volatile("cp.async.wait_group 0;");
        __syncthreads();

        const __half* Ac = As[cur];
        const __half* Bc = Bs[cur];
        #pragma unroll
        for (int s = 0; s < 2; ++s) {
            int kc = 16*s + 2*tig;
            uint32_t a[4][4], b[4][2];
            #pragma unroll
            for (int mt = 0; mt < 4; ++mt) {
                int r0 = 64*wm + 16*mt + gid;
                const __half* b0 = &Ac[r0*KBP + kc];
                const __half* b1 = &Ac[(r0+8)*KBP + kc];
                a[mt][0] = ldh32(b0);
                a[mt][1] = ldh32(b1);
                a[mt][2] = ldh32(b0 + 8);
                a[mt][3] = ldh32(b1 + 8);
            }
            #pragma unroll
            for (int nt = 0; nt < 4; ++nt) {
                int n0 = 32*wn + 8*nt + gid;
                const __half* bb = &Bc[n0*KBP + kc];
                b[nt][0] = ldh32(bb);
                b[nt][1] = ldh32(bb + 8);
            }
            #pragma unroll
            for (int mt = 0; mt < 4; ++mt)
                #pragma unroll
                for (int nt = 0; nt < 4; ++nt)
                    mma16(acc[mt][nt], a[mt], b[nt]);
        }
        __syncthreads();

        if (kt + 2 < 16) load_chunk(cur, (kt + 2) * 32);
    }

    #pragma unroll
    for (int mt = 0; mt < 4; ++mt) {
        int r0 = i0 + 64*wm + 16*mt + gid;
        #pragma unroll
        for (int nt = 0; nt < 4; ++nt) {
            int cb = j0 + 32*wn + 8*nt + 2*tig;
            *(float2*)&T[(size_t)r0*NN + cb]     = make_float2(acc[mt][nt][0], acc[mt][nt][1]);
            *(float2*)&T[(size_t)(r0+8)*NN + cb] = make_float2(acc[mt][nt][2], acc[mt][nt][3]);
        }
    }
}

// ---------------------------------------------------------------------------
// Kernel C: LN2(tri)@Wo^T * sigmoid(LN1(pair)@Wgl^T) + pair  (fp16 MMA)
// CTA: 512 threads, 128 positions.
// smem: t32[128*132] f32 (then reused as wh), th[128*HP] h, xh[128*HP] h
// ---------------------------------------------------------------------------
#define T32_PAD 132
#define KC_T32_BYTES (128*T32_PAD*4)
#define KC_SMEM (KC_T32_BYTES + 2*(128*HP)*2 + 16)

__global__ void __launch_bounds__(512) kC(const float* __restrict__ pair,
                                          const float* __restrict__ w1,
                                          const float* __restrict__ b1,
                                          const float* __restrict__ w2,
                                          const float* __restrict__ b2,
                                          const float* __restrict__ Wo,
                                          const float* __restrict__ Wgl,
                                          float* __restrict__ out)
{
    extern __shared__ char smraw[];
    float*  t32 = (float*)smraw;                        // 128*132 f32
    __half* wh  = (__half*)smraw;                       // aliases t32 (2*64*HP h)
    __half* th  = (__half*)(smraw + KC_T32_BYTES);      // 128*HP
    __half* xh  = th + 128*HP;                          // 128*HP

    const int tid = threadIdx.x;
    const int p0  = blockIdx.x * 128;
    const int warp = tid >> 5, lane = tid & 31;

    // tri tile (transposing gather, coalesced over positions)
    #pragma unroll
    for (int it = 0; it < 32; ++it) {
        int idx = it*512 + tid;
        int r = idx & 127, c = idx >> 7;
        t32[r*T32_PAD + c] = g_t[(size_t)c*NPOS + p0 + r];
    }
    __syncthreads();

    // LN1 on pair (from gmem) -> xh ; LN2 on t32 -> th
    {
        float4 w1v = *(const float4*)&w1[4*lane];
        float4 b1v = *(const float4*)&b1[4*lane];
        float4 w2v = *(const float4*)&w2[4*lane];
        float4 b2v = *(const float4*)&b2[4*lane];
        #pragma unroll
        for (int rr = 0; rr < 8; ++rr) {
            int r = warp*8 + rr;
            {   // pair
                float4 v = *(const float4*)&pair[(size_t)(p0 + r)*CC + 4*lane];
                float s  = v.x+v.y+v.z+v.w;
                float s2 = v.x*v.x+v.y*v.y+v.z*v.z+v.w*v.w;
                #pragma unroll
                for (int o = 16; o; o >>= 1) {
                    s  += __shfl_xor_sync(0xffffffffu, s , o);
                    s2 += __shfl_xor_sync(0xffffffffu, s2, o);
                }
                float mu = s*(1.f/128.f), var = s2*(1.f/128.f) - mu*mu;
                float rstd = rsqrtf(var + 1e-5f);
                *(__half2*)&xh[r*HP + 4*lane] =
                    __floats2half2_rn((v.x-mu)*rstd*w1v.x + b1v.x, (v.y-mu)*rstd*w1v.y + b1v.y);
                *(__half2*)&xh[r*HP + 4*lane + 2] =
                    __floats2half2_rn((v.z-mu)*rstd*w1v.z + b1v.z, (v.w-mu)*rstd*w1v.w + b1v.w);
            }
            {   // tri
                float v0 = t32[r*T32_PAD + 4*lane    ];
                float v1 = t32[r*T32_PAD + 4*lane + 1];
                float v2 = t32[r*T32_PAD + 4*lane + 2];
                float v3 = t32[r*T32_PAD + 4*lane + 3];
                float s  = v0+v1+v2+v3;
                float s2 = v0*v0+v1*v1+v2*v2+v3*v3;
                #pragma unroll
                for (int o = 16; o; o >>= 1) {
                    s  += __shfl_xor_sync(0xffffffffu, s , o);
                    s2 += __shfl_xor_sync(0xffffffffu, s2, o);
                }
                float mu = s*(1.f/128.f), var = s2*(1.f/128.f) - mu*mu;
                float rstd = rsqrtf(var + 1e-5f);
                *(__half2*)&th[r*HP + 4*lane] =
                    __floats2half2_rn((v0-mu)*rstd*w2v.x + b2v.x, (v1-mu)*rstd*w2v.y + b2v.y);
                *(__half2*)&th[r*HP + 4*lane + 2] =
                    __floats2half2_rn((v2-mu)*rstd*w2v.z + b2v.z, (v3-mu)*rstd*w2v.w + b2v.w);
            }
        }
    }
    __syncthreads();

    const int wm = warp & 3;
    const int wn = warp >> 2;
    const int gid = lane >> 2, tig = lane & 3;

    for (int o0 = 0; o0 < 128; o0 += 64) {
        // weight chunk -> fp16 smem (aliases t32, safe after sync)
        #pragma unroll
        for (int it = 0; it < 16; ++it) {
            int idx = it*512 + tid;
            int n = idx >> 7, k = idx & 127;
            wh[n*HP + k]         = __float2half_rn(Wo [(size_t)(o0+n)*CC + k]);
            wh[64*HP + n*HP + k] = __float2half_rn(Wgl[(size_t)(o0+n)*CC + k]);
        }
        __syncthreads();

        float accO[2][2][4] = {}, accG[2][2][4] = {};

        #pragma unroll
        for (int kk = 0; kk < 128; kk += 16) {
            uint32_t at[2][4], ax[2][4];
            #pragma unroll
            for (int mt = 0; mt < 2; ++mt) {
                int r0 = 32*wm + 16*mt + gid;
                const __half* t0 = &th[r0*HP + kk + 2*tig];
                const __half* t1 = &th[(r0+8)*HP + kk + 2*tig];
                const __half* x0 = &xh[r0*HP + kk + 2*tig];
                const __half* x1 = &xh[(r0+8)*HP + kk + 2*tig];
                at[mt][0] = ldh32(t0); at[mt][1] = ldh32(t1);
                at[mt][2] = ldh32(t0 + 8); at[mt][3] = ldh32(t1 + 8);
                ax[mt][0] = ldh32(x0); ax[mt][1] = ldh32(x1);
                ax[mt][2] = ldh32(x0 + 8); ax[mt][3] = ldh32(x1 + 8);
            }
            uint32_t bo[2][2], bg[2][2];
            #pragma unroll
            for (int nt = 0; nt < 2; ++nt) {
                int n0 = 16*wn + 8*nt + gid;
                const __half* ob = &wh[n0*HP + kk + 2*tig];
                const __half* gb = &wh[64*HP + n0*HP + kk + 2*tig];
                bo[nt][0] = ldh32(ob); bo[nt][1] = ldh32(ob + 8);
                bg[nt][0] = ldh32(gb); bg[nt][1] = ldh32(gb + 8);
            }
            #pragma unroll
            for (int mt = 0; mt < 2; ++mt)
                #pragma unroll
                for (int nt = 0; nt < 2; ++nt) {
                    mma16(accO[mt][nt], at[mt], bo[nt]);
                    mma16(accG[mt][nt], ax[mt], bg[nt]);
                }
        }
        __syncthreads();

        #pragma unroll
        for (int mt = 0; mt < 2; ++mt) {
            int rl0 = 32*wm + 16*mt + gid;
            #pragma unroll
            for (int nt = 0; nt < 2; ++nt) {
                int col = o0 + 16*wn + 8*nt + 2*tig;
                const float* O = accO[mt][nt];
                const float* G = accG[mt][nt];
                {
                    size_t a0 = (size_t)(p0 + rl0)*CC + col;
                    float2 pr = *(const float2*)&pair[a0];
                    float2 ov;
                    ov.x = pr.x + O[0] * sigm(G[0]);
                    ov.y = pr.y + O[1] * sigm(G[1]);
                    *(float2*)&out[a0] = ov;
                }
                {
                    size_t a1 = (size_t)(p0 + rl0 + 8)*CC + col;
                    float2 pr = *(const float2*)&pair[a1];
                    float2 ov;
                    ov.x = pr.x + O[2] * sigm(G[2]);
                    ov.y = pr.y + O[3] * sigm(G[3]);
                    *(float2*)&out[a1] = ov;
                }
            }
        }
    }
}

// ---------------------------------------------------------------------------
extern "C" void kernel_launch(void* const* d_in, const int* in_sizes, int n_in,
                              void* d_out, int out_size)
{
    const float* pair = (const float*)d_in[0];
    const float* mask = (const float*)d_in[1];
    const float* w1   = (const float*)d_in[2];
    const float* b1   = (const float*)d_in[3];
    const float* Wp   = (const float*)d_in[4];
    const float* Wg   = (const float*)d_in[5];
    const float* w2   = (const float*)d_in[6];
    const float* b2   = (const float*)d_in[7];
    const float* Wo   = (const float*)d_in[8];
    const float* Wgl  = (const float*)d_in[9];
    float* out = (float*)d_out;

    cudaFuncSetAttribute(kA, cudaFuncAttributeMaxDynamicSharedMemorySize, (int)KA_SMEM);
    cudaFuncSetAttribute(kC, cudaFuncAttributeMaxDynamicSharedMemorySize, (int)KC_SMEM);

    kA<<<NPOS/128, 512, KA_SMEM>>>(pair, mask, w1, b1, Wp, Wg);
    kB<<<dim3(NN/128, NN/128, CC), 256>>>();
    kC<<<NPOS/128, 512, KC_SMEM>>>(pair, w1, b1, w2, b2, Wo, Wgl, out);
}

// round 7
// speedup vs baseline: 5.5646x; 1.1586x over previous
#include <cuda_runtime.h>
#include <cuda_fp16.h>
#include <math.h>
#include <stdint.h>

#define NN 512
#define CC 128
#define NPOS (NN*NN)

__device__ __half g_a[(size_t)CC * NPOS];
__device__ __half g_b[(size_t)CC * NPOS];
__device__ float  g_t[(size_t)CC * NPOS];

// ---------------------------------------------------------------------------
// helpers
// ---------------------------------------------------------------------------
__device__ __forceinline__ void mma16(float* d, const uint32_t* a, const uint32_t* b) {
    asm volatile(
        "mma.sync.aligned.m16n8k16.row.col.f32.f16.f16.f32 "
        "{%0,%1,%2,%3}, {%4,%5,%6,%7}, {%8,%9}, {%0,%1,%2,%3};\n"
        : "+f"(d[0]), "+f"(d[1]), "+f"(d[2]), "+f"(d[3])
        : "r"(a[0]), "r"(a[1]), "r"(a[2]), "r"(a[3]), "r"(b[0]), "r"(b[1]));
}
__device__ __forceinline__ void ldsm4(uint32_t* r, uint32_t addr) {
    asm volatile("ldmatrix.sync.aligned.m8n8.x4.shared.b16 {%0,%1,%2,%3}, [%4];"
                 : "=r"(r[0]), "=r"(r[1]), "=r"(r[2]), "=r"(r[3]) : "r"(addr));
}
__device__ __forceinline__ float sigm(float x) {
    return __fdividef(1.f, 1.f + __expf(-x));
}
__device__ __forceinline__ uint32_t sptr(const void* p) {
    return (uint32_t)__cvta_generic_to_shared(p);
}
__device__ __forceinline__ void cpa16(uint32_t dst, const void* src) {
    asm volatile("cp.async.cg.shared.global [%0], [%1], 16;" :: "r"(dst), "l"(src));
}

#define HP 136   // half pad: 272B rows, ldmatrix conflict-free

// ---------------------------------------------------------------------------
// Kernel A: LN1 + fp16 MMA vs Wp/Wg + mask*sigmoid + split
// CTA: 256 threads (8 warps), 128 positions, 2 CTAs/SM.
// warp grid: wm=warp&3 (32 rows), wn=warp>>2 (32 cols of the 64-chunk)
// ---------------------------------------------------------------------------
#define KA_SMEM ((128*HP + 2*64*HP)*2 + 128*4 + 16)

__global__ void __launch_bounds__(256, 2) kA(const float* __restrict__ pair,
                                             const float* __restrict__ mask,
                                             const float* __restrict__ w1,
                                             const float* __restrict__ b1,
                                             const float* __restrict__ Wp,
                                             const float* __restrict__ Wg)
{
    extern __shared__ char smraw[];
    __half* xh  = (__half*)smraw;                 // 128*HP
    __half* wh  = xh + 128*HP;                    // 2 * 64*HP
    float* mrow = (float*)(wh + 2*64*HP);         // 128

    const int tid = threadIdx.x;
    const int p0  = blockIdx.x * 128;
    const int warp = tid >> 5, lane = tid & 31;

    if (tid < 128) mrow[tid] = mask[p0 + tid];

    // LN1: 8 warps x 16 rows
    {
        float4 wv = *(const float4*)&w1[4*lane];
        float4 bv = *(const float4*)&b1[4*lane];
        #pragma unroll
        for (int rr = 0; rr < 16; ++rr) {
            int r = warp*16 + rr;
            float4 v = *(const float4*)&pair[(size_t)(p0 + r)*CC + 4*lane];
            float s  = v.x+v.y+v.z+v.w;
            float s2 = v.x*v.x+v.y*v.y+v.z*v.z+v.w*v.w;
            #pragma unroll
            for (int o = 16; o; o >>= 1) {
                s  += __shfl_xor_sync(0xffffffffu, s , o);
                s2 += __shfl_xor_sync(0xffffffffu, s2, o);
            }
            float mu = s*(1.f/128.f), var = s2*(1.f/128.f) - mu*mu;
            float rstd = rsqrtf(var + 1e-5f);
            *(__half2*)&xh[r*HP + 4*lane] =
                __floats2half2_rn((v.x-mu)*rstd*wv.x + bv.x, (v.y-mu)*rstd*wv.y + bv.y);
            *(__half2*)&xh[r*HP + 4*lane + 2] =
                __floats2half2_rn((v.z-mu)*rstd*wv.z + bv.z, (v.w-mu)*rstd*wv.w + bv.w);
        }
    }
    __syncthreads();

    const int wm = warp & 3;         // rows 32*wm
    const int wn = warp >> 2;        // cols 32*wn within 64-chunk
    const int gid = lane >> 2, tig = lane & 3;
    const int lrow = lane & 7;
    const int am8  = (lane >> 3) & 1;
    const int am16 = (lane >> 4) & 1;

    // ldmatrix base addresses (bytes)
    const uint32_t xb = sptr(xh);
    const uint32_t wb = sptr(wh);
    // A: row = 32*wm + 16*mt + am8*8 + lrow ; col = kk + am16*8
    const uint32_t aab = xb + (uint32_t)(((32*wm + am8*8 + lrow)*HP + am16*8) * 2);
    // B: row = 32*wn + 16*p + am16*8 + lrow ; col = kk + am8*8
    const uint32_t bab = wb + (uint32_t)(((32*wn + am16*8 + lrow)*HP + am8*8) * 2);

    for (int o0 = 0; o0 < 256; o0 += 64) {
        // weight chunk -> fp16 smem (vectorized)
        #pragma unroll
        for (int it = 0; it < 16; ++it) {
            int idx = it*256 + tid;              // 0..4095 (half2 units)
            int n = idx >> 6, k2 = idx & 63;
            float2 pv = *(const float2*)&Wp[(size_t)(o0+n)*CC + 2*k2];
            float2 gv = *(const float2*)&Wg[(size_t)(o0+n)*CC + 2*k2];
            *(__half2*)&wh[n*HP + 2*k2]         = __floats2half2_rn(pv.x, pv.y);
            *(__half2*)&wh[64*HP + n*HP + 2*k2] = __floats2half2_rn(gv.x, gv.y);
        }
        __syncthreads();

        float accP[2][4][4] = {}, accG[2][4][4] = {};

        #pragma unroll
        for (int kk = 0; kk < 128; kk += 16) {
            uint32_t a[2][4], bp[2][4], bg[2][4];
            ldsm4(a[0], aab + (uint32_t)(kk*2));
            ldsm4(a[1], aab + (uint32_t)((16*HP + kk)*2));
            ldsm4(bp[0], bab + (uint32_t)(kk*2));
            ldsm4(bp[1], bab + (uint32_t)((16*HP + kk)*2));
            ldsm4(bg[0], bab + (uint32_t)((64*HP + kk)*2));
            ldsm4(bg[1], bab + (uint32_t)((80*HP + kk)*2));
            #pragma unroll
            for (int mt = 0; mt < 2; ++mt)
                #pragma unroll
                for (int nt = 0; nt < 4; ++nt) {
                    mma16(accP[mt][nt], a[mt], &bp[nt>>1][2*(nt&1)]);
                    mma16(accG[mt][nt], a[mt], &bg[nt>>1][2*(nt&1)]);
                }
        }
        __syncthreads();     // done with wh -> reuse as stage

        __half* stage = wh;
        #pragma unroll
        for (int mt = 0; mt < 2; ++mt) {
            int rl0 = 32*wm + 16*mt + gid;
            int rl1 = rl0 + 8;
            float m0 = mrow[rl0], m1 = mrow[rl1];
            #pragma unroll
            for (int nt = 0; nt < 4; ++nt) {
                int cl = 32*wn + 8*nt + 2*tig;
                const float* P = accP[mt][nt];
                const float* G = accG[mt][nt];
                stage[cl*HP + rl0]     = __float2half_rn(P[0] * m0 * sigm(G[0]));
                stage[(cl+1)*HP + rl0] = __float2half_rn(P[1] * m0 * sigm(G[1]));
                stage[cl*HP + rl1]     = __float2half_rn(P[2] * m1 * sigm(G[2]));
                stage[(cl+1)*HP + rl1] = __float2half_rn(P[3] * m1 * sigm(G[3]));
            }
        }
        __syncthreads();

        // coalesced copy out: 64 segments x 64 u32 words
        #pragma unroll
        for (int it = 0; it < 16; ++it) {
            int w = it*256 + tid;                // 0..4095
            int seg = w >> 6, rw = w & 63;
            int og = o0 + seg;
            uint32_t val = *(const uint32_t*)&stage[seg*HP + 2*rw];
            __half* dst = (og & 1) ? g_b : g_a;
            *(uint32_t*)&dst[(size_t)(og >> 1)*NPOS + p0 + 2*rw] = val;
        }
        __syncthreads();
    }
}

// ---------------------------------------------------------------------------
// Kernel B: per-channel NT fp16 GEMM  T_c = A_c @ B_c^T (fp32 accum)
// CTA: 256 thr, 128x128 tile, K-chunk 32, cp.async double buffer, ldmatrix.
// ---------------------------------------------------------------------------
#define KBP 40

__global__ void __launch_bounds__(256, 2) kB()
{
    const int c  = blockIdx.z;
    const __half* __restrict__ A = g_a + (size_t)c * NPOS;
    const __half* __restrict__ B = g_b + (size_t)c * NPOS;
    float* __restrict__ T = g_t + (size_t)c * NPOS;
    const int i0 = blockIdx.y * 128;
    const int j0 = blockIdx.x * 128;

    __shared__ __half As[2][128*KBP];
    __shared__ __half Bs[2][128*KBP];
    const uint32_t sA = sptr(&As[0][0]);
    const uint32_t sB = sptr(&Bs[0][0]);

    const int tid = threadIdx.x;
    const int warp = tid >> 5, lane = tid & 31;
    const int wm = warp & 1;
    const int wn = warp >> 1;
    const int gid = lane >> 2, tig = lane & 3;
    const int lrow = lane & 7;
    const int am8  = (lane >> 3) & 1;
    const int am16 = (lane >> 4) & 1;

    // per-buffer fragment base offsets (bytes, without buffer offset)
    const uint32_t aoff = (uint32_t)(((64*wm + am8*8 + lrow)*KBP + am16*8) * 2);
    const uint32_t boff = (uint32_t)(((32*wn + am16*8 + lrow)*KBP + am8*8) * 2);
    const uint32_t bufbytes = 128*KBP*2;

    float acc[4][4][4] = {};

    auto load_chunk = [&](int buf, int k0) {
        const uint32_t bo = (uint32_t)(buf * bufbytes);
        #pragma unroll
        for (int it = 0; it < 2; ++it) {
            int idx = it*256 + tid;
            int row = idx >> 2, g = idx & 3;
            uint32_t doff = (uint32_t)(row*KBP*2 + g*16);
            cpa16(sA + bo + doff, &A[(size_t)(i0+row)*NN + k0 + g*8]);
            cpa16(sB + bo + doff, &B[(size_t)(j0+row)*NN + k0 + g*8]);
        }
        asm volatile("cp.async.commit_group;");
    };

    load_chunk(0, 0);
    load_chunk(1, 32);

    #pragma unroll 1
    for (int kt = 0; kt < 16; ++kt) {
        const int cur = kt & 1;
        if (kt < 15) asm volatile("cp.async.wait_group 1;");
        else         asm volatile("cp.async.wait_group 0;");
        __syncthreads();

        const uint32_t cb = (uint32_t)(cur * bufbytes);
        #pragma unroll
        for (int s = 0; s < 2; ++s) {
            const uint32_t ks = (uint32_t)(s * 16 * 2);
            uint32_t a[4][4], bq[2][4];
            #pragma unroll
            for (int mt = 0; mt < 4; ++mt)
                ldsm4(a[mt], sA + cb + aoff + (uint32_t)(16*mt*KBP*2) + ks);
            ldsm4(bq[0], sB + cb + boff + ks);
            ldsm4(bq[1], sB + cb + boff + (uint32_t)(16*KBP*2) + ks);
            #pragma unroll
            for (int mt = 0; mt < 4; ++mt)
                #pragma unroll
                for (int nt = 0; nt < 4; ++nt)
                    mma16(acc[mt][nt], a[mt], &bq[nt>>1][2*(nt&1)]);
        }
        __syncthreads();

        if (kt + 2 < 16) load_chunk(cur, (kt + 2) * 32);
    }

    #pragma unroll
    for (int mt = 0; mt < 4; ++mt) {
        int r0 = i0 + 64*wm + 16*mt + gid;
        #pragma unroll
        for (int nt = 0; nt < 4; ++nt) {
            int cbn = j0 + 32*wn + 8*nt + 2*tig;
            *(float2*)&T[(size_t)r0*NN + cbn]     = make_float2(acc[mt][nt][0], acc[mt][nt][1]);
            *(float2*)&T[(size_t)(r0+8)*NN + cbn] = make_float2(acc[mt][nt][2], acc[mt][nt][3]);
        }
    }
}

// ---------------------------------------------------------------------------
// Kernel C: LN2(tri)@Wo^T * sigmoid(LN1(pair)@Wgl^T) + pair
// CTA: 256 threads (8 warps), 64 positions, 2 CTAs/SM.
// smem: t32[64][132] f32, wh[2*64*HP] h, th[64*HP] h, xh[64*HP] h
// ---------------------------------------------------------------------------
#define T32_PAD 132
#define KC_T32B (64*T32_PAD*4)
#define KC_SMEM (KC_T32B + (2*64*HP)*2 + 2*(64*HP)*2 + 16)

__global__ void __launch_bounds__(256, 2) kC(const float* __restrict__ pair,
                                             const float* __restrict__ w1,
                                             const float* __restrict__ b1,
                                             const float* __restrict__ w2,
                                             const float* __restrict__ b2,
                                             const float* __restrict__ Wo,
                                             const float* __restrict__ Wgl,
                                             float* __restrict__ out)
{
    extern __shared__ char smraw[];
    float*  t32 = (float*)smraw;                          // 64*132 f32
    __half* wh  = (__half*)(smraw + KC_T32B);             // 2*64*HP
    __half* th  = wh + 2*64*HP;                           // 64*HP
    __half* xh  = th + 64*HP;                             // 64*HP

    const int tid = threadIdx.x;
    const int p0  = blockIdx.x * 64;
    const int warp = tid >> 5, lane = tid & 31;

    // tri tile gather (coalesced over positions)
    #pragma unroll
    for (int it = 0; it < 32; ++it) {
        int idx = it*256 + tid;                  // 0..8191
        int r = idx & 63, c = idx >> 6;
        t32[r*T32_PAD + c] = g_t[(size_t)c*NPOS + p0 + r];
    }
    __syncthreads();

    // LN1(pair) -> xh, LN2(t32) -> th: 8 warps x 8 rows
    {
        float4 w1v = *(const float4*)&w1[4*lane];
        float4 b1v = *(const float4*)&b1[4*lane];
        float4 w2v = *(const float4*)&w2[4*lane];
        float4 b2v = *(const float4*)&b2[4*lane];
        #pragma unroll
        for (int rr = 0; rr < 8; ++rr) {
            int r = warp*8 + rr;
            {
                float4 v = *(const float4*)&pair[(size_t)(p0 + r)*CC + 4*lane];
                float s  = v.x+v.y+v.z+v.w;
                float s2 = v.x*v.x+v.y*v.y+v.z*v.z+v.w*v.w;
                #pragma unroll
                for (int o = 16; o; o >>= 1) {
                    s  += __shfl_xor_sync(0xffffffffu, s , o);
                    s2 += __shfl_xor_sync(0xffffffffu, s2, o);
                }
                float mu = s*(1.f/128.f), var = s2*(1.f/128.f) - mu*mu;
                float rstd = rsqrtf(var + 1e-5f);
                *(__half2*)&xh[r*HP + 4*lane] =
                    __floats2half2_rn((v.x-mu)*rstd*w1v.x + b1v.x, (v.y-mu)*rstd*w1v.y + b1v.y);
                *(__half2*)&xh[r*HP + 4*lane + 2] =
                    __floats2half2_rn((v.z-mu)*rstd*w1v.z + b1v.z, (v.w-mu)*rstd*w1v.w + b1v.w);
            }
            {
                float v0 = t32[r*T32_PAD + 4*lane    ];
                float v1 = t32[r*T32_PAD + 4*lane + 1];
                float v2 = t32[r*T32_PAD + 4*lane + 2];
                float v3 = t32[r*T32_PAD + 4*lane + 3];
                float s  = v0+v1+v2+v3;
                float s2 = v0*v0+v1*v1+v2*v2+v3*v3;
                #pragma unroll
                for (int o = 16; o; o >>= 1) {
                    s  += __shfl_xor_sync(0xffffffffu, s , o);
                    s2 += __shfl_xor_sync(0xffffffffu, s2, o);
                }
                float mu = s*(1.f/128.f), var = s2*(1.f/128.f) - mu*mu;
                float rstd = rsqrtf(var + 1e-5f);
                *(__half2*)&th[r*HP + 4*lane] =
                    __floats2half2_rn((v0-mu)*rstd*w2v.x + b2v.x, (v1-mu)*rstd*w2v.y + b2v.y);
                *(__half2*)&th[r*HP + 4*lane + 2] =
                    __floats2half2_rn((v2-mu)*rstd*w2v.z + b2v.z, (v3-mu)*rstd*w2v.w + b2v.w);
            }
        }
    }
    __syncthreads();

    const int wm = warp & 1;         // rows 32*wm
    const int wn = warp >> 1;        // cols 16*wn within 64-chunk
    const int gid = lane >> 2, tig = lane & 3;
    const int lrow = lane & 7;
    const int am8  = (lane >> 3) & 1;
    const int am16 = (lane >> 4) & 1;

    const uint32_t tb = sptr(th);
    const uint32_t xbb = sptr(xh);
    const uint32_t wb = sptr(wh);
    const uint32_t atb = tb  + (uint32_t)(((32*wm + am8*8 + lrow)*HP + am16*8) * 2);
    const uint32_t axb = xbb + (uint32_t)(((32*wm + am8*8 + lrow)*HP + am16*8) * 2);
    const uint32_t bbb = wb  + (uint32_t)(((16*wn + am16*8 + lrow)*HP + am8*8) * 2);

    for (int o0 = 0; o0 < 128; o0 += 64) {
        #pragma unroll
        for (int it = 0; it < 16; ++it) {
            int idx = it*256 + tid;              // 0..4095 (half2 units)
            int n = idx >> 6, k2 = idx & 63;
            float2 ov = *(const float2*)&Wo [(size_t)(o0+n)*CC + 2*k2];
            float2 gv = *(const float2*)&Wgl[(size_t)(o0+n)*CC + 2*k2];
            *(__half2*)&wh[n*HP + 2*k2]         = __floats2half2_rn(ov.x, ov.y);
            *(__half2*)&wh[64*HP + n*HP + 2*k2] = __floats2half2_rn(gv.x, gv.y);
        }
        __syncthreads();

        float accO[2][2][4] = {}, accG[2][2][4] = {};

        #pragma unroll
        for (int kk = 0; kk < 128; kk += 16) {
            uint32_t at[2][4], ax[2][4], bo[4], bg[4];
            ldsm4(at[0], atb + (uint32_t)(kk*2));
            ldsm4(at[1], atb + (uint32_t)((16*HP + kk)*2));
            ldsm4(ax[0], axb + (uint32_t)(kk*2));
            ldsm4(ax[1], axb + (uint32_t)((16*HP + kk)*2));
            ldsm4(bo, bbb + (uint32_t)(kk*2));
            ldsm4(bg, bbb + (uint32_t)((64*HP + kk)*2));
            #pragma unroll
            for (int mt = 0; mt < 2; ++mt)
                #pragma unroll
                for (int nt = 0; nt < 2; ++nt) {
                    mma16(accO[mt][nt], at[mt], &bo[2*nt]);
                    mma16(accG[mt][nt], ax[mt], &bg[2*nt]);
                }
        }
        __syncthreads();

        #pragma unroll
        for (int mt = 0; mt < 2; ++mt) {
            int rl0 = 32*wm + 16*mt + gid;
            #pragma unroll
            for (int nt = 0; nt < 2; ++nt) {
                int col = o0 + 16*wn + 8*nt + 2*tig;
                const float* O = accO[mt][nt];
                const float* G = accG[mt][nt];
                {
                    size_t a0 = (size_t)(p0 + rl0)*CC + col;
                    float2 pr = *(const float2*)&pair[a0];
                    float2 ov;
                    ov.x = pr.x + O[0] * sigm(G[0]);
                    ov.y = pr.y + O[1] * sigm(G[1]);
                    *(float2*)&out[a0] = ov;
                }
                {
                    size_t a1 = (size_t)(p0 + rl0 + 8)*CC + col;
                    float2 pr = *(const float2*)&pair[a1];
                    float2 ov;
                    ov.x = pr.x + O[2] * sigm(G[2]);
                    ov.y = pr.y + O[3] * sigm(G[3]);
                    *(float2*)&out[a1] = ov;
                }
            }
        }
    }
}

// ---------------------------------------------------------------------------
extern "C" void kernel_launch(void* const* d_in, const int* in_sizes, int n_in,
                              void* d_out, int out_size)
{
    const float* pair = (const float*)d_in[0];
    const float* mask = (const float*)d_in[1];
    const float* w1   = (const float*)d_in[2];
    const float* b1   = (const float*)d_in[3];
    const float* Wp   = (const float*)d_in[4];
    const float* Wg   = (const float*)d_in[5];
    const float* w2   = (const float*)d_in[6];
    const float* b2   = (const float*)d_in[7];
    const float* Wo   = (const float*)d_in[8];
    const float* Wgl  = (const float*)d_in[9];
    float* out = (float*)d_out;

    cudaFuncSetAttribute(kA, cudaFuncAttributeMaxDynamicSharedMemorySize, (int)KA_SMEM);
    cudaFuncSetAttribute(kC, cudaFuncAttributeMaxDynamicSharedMemorySize, (int)KC_SMEM);

    kA<<<NPOS/128, 256, KA_SMEM>>>(pair, mask, w1, b1, Wp, Wg);
    kB<<<dim3(NN/128, NN/128, CC), 256>>>();
    kC<<<NPOS/64, 256, KC_SMEM>>>(pair, w1, b1, w2, b2, Wo, Wgl, out);
}

// round 8
// speedup vs baseline: 5.9956x; 1.0775x over previous
#include <cuda_runtime.h>
#include <cuda_fp16.h>
#include <math.h>
#include <stdint.h>

#define NN 512
#define CC 128
#define NPOS (NN*NN)

__device__ __half g_a[(size_t)CC * NPOS];
__device__ __half g_b[(size_t)CC * NPOS];
__device__ float  g_t[(size_t)CC * NPOS];

// fp16 weight copies (filled by kW once per launch)
__device__ __half g_wp[256*128];
__device__ __half g_wg[256*128];
__device__ __half g_wo[128*128];
__device__ __half g_wgl[128*128];

// ---------------------------------------------------------------------------
// helpers
// ---------------------------------------------------------------------------
__device__ __forceinline__ void mma16(float* d, const uint32_t* a, const uint32_t* b) {
    asm volatile(
        "mma.sync.aligned.m16n8k16.row.col.f32.f16.f16.f32 "
        "{%0,%1,%2,%3}, {%4,%5,%6,%7}, {%8,%9}, {%0,%1,%2,%3};\n"
        : "+f"(d[0]), "+f"(d[1]), "+f"(d[2]), "+f"(d[3])
        : "r"(a[0]), "r"(a[1]), "r"(a[2]), "r"(a[3]), "r"(b[0]), "r"(b[1]));
}
__device__ __forceinline__ void ldsm4(uint32_t* r, uint32_t addr) {
    asm volatile("ldmatrix.sync.aligned.m8n8.x4.shared.b16 {%0,%1,%2,%3}, [%4];"
                 : "=r"(r[0]), "=r"(r[1]), "=r"(r[2]), "=r"(r[3]) : "r"(addr));
}
__device__ __forceinline__ float sigm(float x) {
    return __fdividef(1.f, 1.f + __expf(-x));
}
__device__ __forceinline__ uint32_t sptr(const void* p) {
    return (uint32_t)__cvta_generic_to_shared(p);
}
__device__ __forceinline__ void cpa16(uint32_t dst, const void* src) {
    asm volatile("cp.async.cg.shared.global [%0], [%1], 16;" :: "r"(dst), "l"(src));
}

#define HP 136   // half pad: 272B rows, ldmatrix conflict-free

// ---------------------------------------------------------------------------
// kW: convert weights to fp16 once (32768 threads)
// ---------------------------------------------------------------------------
__global__ void __launch_bounds__(256) kW(const float* __restrict__ Wp,
                                          const float* __restrict__ Wg,
                                          const float* __restrict__ Wo,
                                          const float* __restrict__ Wgl)
{
    int idx = blockIdx.x * 256 + threadIdx.x;      // 0..32767
    g_wp[idx] = __float2half_rn(Wp[idx]);
    g_wg[idx] = __float2half_rn(Wg[idx]);
    if (idx < 16384) {
        g_wo [idx] = __float2half_rn(Wo [idx]);
        g_wgl[idx] = __float2half_rn(Wgl[idx]);
    }
}

// ---------------------------------------------------------------------------
// Kernel A: LN1 + fp16 MMA vs Wp/Wg + mask*sigmoid + split
// CTA: 256 threads, 128 positions, 2 CTAs/SM.
// smem: xh[128*HP]h, wh[128*HP]h (single weight buffer: Wp|Wg chunk),
//       stage[64*HP]h, mrow[128]f
// cp.async pipelines chunk i+1 weights under chunk i epilogue.
// ---------------------------------------------------------------------------
#define KA_SMEM ((128*HP + 128*HP + 64*HP)*2 + 128*4 + 16)

__global__ void __launch_bounds__(256, 2) kA(const float* __restrict__ pair,
                                             const float* __restrict__ mask,
                                             const float* __restrict__ w1,
                                             const float* __restrict__ b1)
{
    extern __shared__ char smraw[];
    __half* xh    = (__half*)smraw;               // 128*HP
    __half* wh    = xh + 128*HP;                  // 128*HP (wp 64 rows | wg 64 rows)
    __half* stage = wh + 128*HP;                  // 64*HP
    float*  mrow  = (float*)(stage + 64*HP);      // 128

    const int tid = threadIdx.x;
    const int p0  = blockIdx.x * 128;
    const int warp = tid >> 5, lane = tid & 31;
    const uint32_t whb = sptr(wh);

    auto load_w = [&](int o0) {
        #pragma unroll
        for (int it = 0; it < 8; ++it) {
            int idx = it*256 + tid;               // 0..2047
            int m = idx >> 10, j = idx & 1023;
            int n = j >> 4, g = j & 15;
            const __half* src = (m ? g_wg : g_wp) + (size_t)(o0+n)*CC + g*8;
            cpa16(whb + (uint32_t)((m*64*HP + n*HP + g*8) * 2), src);
        }
        asm volatile("cp.async.commit_group;");
    };

    load_w(0);                                    // chunk 0 hides under LN

    if (tid < 128) mrow[tid] = mask[p0 + tid];

    // LN1: 8 warps x 16 rows
    {
        float4 wv = *(const float4*)&w1[4*lane];
        float4 bv = *(const float4*)&b1[4*lane];
        #pragma unroll
        for (int rr = 0; rr < 16; ++rr) {
            int r = warp*16 + rr;
            float4 v = *(const float4*)&pair[(size_t)(p0 + r)*CC + 4*lane];
            float s  = v.x+v.y+v.z+v.w;
            float s2 = v.x*v.x+v.y*v.y+v.z*v.z+v.w*v.w;
            #pragma unroll
            for (int o = 16; o; o >>= 1) {
                s  += __shfl_xor_sync(0xffffffffu, s , o);
                s2 += __shfl_xor_sync(0xffffffffu, s2, o);
            }
            float mu = s*(1.f/128.f), var = s2*(1.f/128.f) - mu*mu;
            float rstd = rsqrtf(var + 1e-5f);
            *(__half2*)&xh[r*HP + 4*lane] =
                __floats2half2_rn((v.x-mu)*rstd*wv.x + bv.x, (v.y-mu)*rstd*wv.y + bv.y);
            *(__half2*)&xh[r*HP + 4*lane + 2] =
                __floats2half2_rn((v.z-mu)*rstd*wv.z + bv.z, (v.w-mu)*rstd*wv.w + bv.w);
        }
    }

    const int wm = warp & 3;         // rows 32*wm
    const int wn = warp >> 2;        // cols 32*wn within 64-chunk
    const int gid = lane >> 2, tig = lane & 3;
    const int lrow = lane & 7;
    const int am8  = (lane >> 3) & 1;
    const int am16 = (lane >> 4) & 1;

    const uint32_t xb = sptr(xh);
    const uint32_t aab = xb  + (uint32_t)(((32*wm + am8*8 + lrow)*HP + am16*8) * 2);
    const uint32_t bab = whb + (uint32_t)(((32*wn + am16*8 + lrow)*HP + am8*8) * 2);

    for (int oc = 0; oc < 4; ++oc) {
        const int o0 = oc * 64;
        asm volatile("cp.async.wait_group 0;");
        __syncthreads();   // weights ready (and xh on first pass)

        float accP[2][4][4] = {}, accG[2][4][4] = {};

        #pragma unroll
        for (int kk = 0; kk < 128; kk += 16) {
            uint32_t a[2][4], bp[2][4], bg[2][4];
            ldsm4(a[0], aab + (uint32_t)(kk*2));
            ldsm4(a[1], aab + (uint32_t)((16*HP + kk)*2));
            ldsm4(bp[0], bab + (uint32_t)(kk*2));
            ldsm4(bp[1], bab + (uint32_t)((16*HP + kk)*2));
            ldsm4(bg[0], bab + (uint32_t)((64*HP + kk)*2));
            ldsm4(bg[1], bab + (uint32_t)((80*HP + kk)*2));
            #pragma unroll
            for (int mt = 0; mt < 2; ++mt)
                #pragma unroll
                for (int nt = 0; nt < 4; ++nt) {
                    mma16(accP[mt][nt], a[mt], &bp[nt>>1][2*(nt&1)]);
                    mma16(accG[mt][nt], a[mt], &bg[nt>>1][2*(nt&1)]);
                }
        }
        __syncthreads();   // all done reading wh

        if (oc < 3) load_w(o0 + 64);   // overlaps epilogue below

        #pragma unroll
        for (int mt = 0; mt < 2; ++mt) {
            int rl0 = 32*wm + 16*mt + gid;
            int rl1 = rl0 + 8;
            float m0 = mrow[rl0], m1 = mrow[rl1];
            #pragma unroll
            for (int nt = 0; nt < 4; ++nt) {
                int cl = 32*wn + 8*nt + 2*tig;
                const float* P = accP[mt][nt];
                const float* G = accG[mt][nt];
                stage[cl*HP + rl0]     = __float2half_rn(P[0] * m0 * sigm(G[0]));
                stage[(cl+1)*HP + rl0] = __float2half_rn(P[1] * m0 * sigm(G[1]));
                stage[cl*HP + rl1]     = __float2half_rn(P[2] * m1 * sigm(G[2]));
                stage[(cl+1)*HP + rl1] = __float2half_rn(P[3] * m1 * sigm(G[3]));
            }
        }
        __syncthreads();

        #pragma unroll
        for (int it = 0; it < 16; ++it) {
            int w = it*256 + tid;                // 0..4095
            int seg = w >> 6, rw = w & 63;
            int og = o0 + seg;
            uint32_t val = *(const uint32_t*)&stage[seg*HP + 2*rw];
            __half* dst = (og & 1) ? g_b : g_a;
            *(uint32_t*)&dst[(size_t)(og >> 1)*NPOS + p0 + 2*rw] = val;
        }
        __syncthreads();
    }
}

// ---------------------------------------------------------------------------
// Kernel B: per-channel NT fp16 GEMM  T_c = A_c @ B_c^T (fp32 accum)
// (unchanged from round 7)
// ---------------------------------------------------------------------------
#define KBP 40

__global__ void __launch_bounds__(256, 2) kB()
{
    const int c  = blockIdx.z;
    const __half* __restrict__ A = g_a + (size_t)c * NPOS;
    const __half* __restrict__ B = g_b + (size_t)c * NPOS;
    float* __restrict__ T = g_t + (size_t)c * NPOS;
    const int i0 = blockIdx.y * 128;
    const int j0 = blockIdx.x * 128;

    __shared__ __half As[2][128*KBP];
    __shared__ __half Bs[2][128*KBP];
    const uint32_t sA = sptr(&As[0][0]);
    const uint32_t sB = sptr(&Bs[0][0]);

    const int tid = threadIdx.x;
    const int warp = tid >> 5, lane = tid & 31;
    const int wm = warp & 1;
    const int wn = warp >> 1;
    const int gid = lane >> 2, tig = lane & 3;
    const int lrow = lane & 7;
    const int am8  = (lane >> 3) & 1;
    const int am16 = (lane >> 4) & 1;

    const uint32_t aoff = (uint32_t)(((64*wm + am8*8 + lrow)*KBP + am16*8) * 2);
    const uint32_t boff = (uint32_t)(((32*wn + am16*8 + lrow)*KBP + am8*8) * 2);
    const uint32_t bufbytes = 128*KBP*2;

    float acc[4][4][4] = {};

    auto load_chunk = [&](int buf, int k0) {
        const uint32_t bo = (uint32_t)(buf * bufbytes);
        #pragma unroll
        for (int it = 0; it < 2; ++it) {
            int idx = it*256 + tid;
            int row = idx >> 2, g = idx & 3;
            uint32_t doff = (uint32_t)(row*KBP*2 + g*16);
            cpa16(sA + bo + doff, &A[(size_t)(i0+row)*NN + k0 + g*8]);
            cpa16(sB + bo + doff, &B[(size_t)(j0+row)*NN + k0 + g*8]);
        }
        asm volatile("cp.async.commit_group;");
    };

    load_chunk(0, 0);
    load_chunk(1, 32);

    #pragma unroll 1
    for (int kt = 0; kt < 16; ++kt) {
        const int cur = kt & 1;
        if (kt < 15) asm volatile("cp.async.wait_group 1;");
        else         asm volatile("cp.async.wait_group 0;");
        __syncthreads();

        const uint32_t cb = (uint32_t)(cur * bufbytes);
        #pragma unroll
        for (int s = 0; s < 2; ++s) {
            const uint32_t ks = (uint32_t)(s * 16 * 2);
            uint32_t a[4][4], bq[2][4];
            #pragma unroll
            for (int mt = 0; mt < 4; ++mt)
                ldsm4(a[mt], sA + cb + aoff + (uint32_t)(16*mt*KBP*2) + ks);
            ldsm4(bq[0], sB + cb + boff + ks);
            ldsm4(bq[1], sB + cb + boff + (uint32_t)(16*KBP*2) + ks);
            #pragma unroll
            for (int mt = 0; mt < 4; ++mt)
                #pragma unroll
                for (int nt = 0; nt < 4; ++nt)
                    mma16(acc[mt][nt], a[mt], &bq[nt>>1][2*(nt&1)]);
        }
        __syncthreads();

        if (kt + 2 < 16) load_chunk(cur, (kt + 2) * 32);
    }

    #pragma unroll
    for (int mt = 0; mt < 4; ++mt) {
        int r0 = i0 + 64*wm + 16*mt + gid;
        #pragma unroll
        for (int nt = 0; nt < 4; ++nt) {
            int cbn = j0 + 32*wn + 8*nt + 2*tig;
            *(float2*)&T[(size_t)r0*NN + cbn]     = make_float2(acc[mt][nt][0], acc[mt][nt][1]);
            *(float2*)&T[(size_t)(r0+8)*NN + cbn] = make_float2(acc[mt][nt][2], acc[mt][nt][3]);
        }
    }
}

// ---------------------------------------------------------------------------
// Kernel C: LN2(tri)@Wo^T * sigmoid(LN1(pair)@Wgl^T) + pair
// CTA: 256 threads, 64 positions, 2 CTAs/SM.
// smem: t32[64][132] f32 (tri, then reused as pair-residual cache),
//       wh[128*HP] h (single Wo|Wgl chunk), th[64*HP] h, xh[64*HP] h
// ---------------------------------------------------------------------------
#define T32_PAD 132
#define KC_T32B (64*T32_PAD*4)
#define KC_SMEM (KC_T32B + (128*HP)*2 + 2*(64*HP)*2 + 16)

__global__ void __launch_bounds__(256, 2) kC(const float* __restrict__ pair,
                                             const float* __restrict__ w1,
                                             const float* __restrict__ b1,
                                             const float* __restrict__ w2,
                                             const float* __restrict__ b2,
                                             float* __restrict__ out)
{
    extern __shared__ char smraw[];
    float*  t32 = (float*)smraw;                          // 64*132 f32
    __half* wh  = (__half*)(smraw + KC_T32B);             // 128*HP
    __half* th  = wh + 128*HP;                            // 64*HP
    __half* xh  = th + 64*HP;                             // 64*HP

    const int tid = threadIdx.x;
    const int p0  = blockIdx.x * 64;
    const int warp = tid >> 5, lane = tid & 31;
    const uint32_t whb = sptr(wh);

    auto load_w = [&](int o0) {
        #pragma unroll
        for (int it = 0; it < 8; ++it) {
            int idx = it*256 + tid;               // 0..2047
            int m = idx >> 10, j = idx & 1023;
            int n = j >> 4, g = j & 15;
            const __half* src = (m ? g_wgl : g_wo) + (size_t)(o0+n)*CC + g*8;
            cpa16(whb + (uint32_t)((m*64*HP + n*HP + g*8) * 2), src);
        }
        asm volatile("cp.async.commit_group;");
    };

    load_w(0);    // chunk 0 weights hide under gather + LN

    // tri tile gather (coalesced over positions)
    #pragma unroll
    for (int it = 0; it < 32; ++it) {
        int idx = it*256 + tid;                  // 0..8191
        int r = idx & 63, c = idx >> 6;
        t32[r*T32_PAD + c] = g_t[(size_t)c*NPOS + p0 + r];
    }
    __syncthreads();

    // LN2(t32)->th first, then LN1(pair)->xh and park pair f32 into t32 row
    {
        float4 w1v = *(const float4*)&w1[4*lane];
        float4 b1v = *(const float4*)&b1[4*lane];
        float4 w2v = *(const float4*)&w2[4*lane];
        float4 b2v = *(const float4*)&b2[4*lane];
        #pragma unroll
        for (int rr = 0; rr < 8; ++rr) {
            int r = warp*8 + rr;
            {   // tri LN2 (consumes t32 row)
                float v0 = t32[r*T32_PAD + 4*lane    ];
                float v1 = t32[r*T32_PAD + 4*lane + 1];
                float v2 = t32[r*T32_PAD + 4*lane + 2];
                float v3 = t32[r*T32_PAD + 4*lane + 3];
                float s  = v0+v1+v2+v3;
                float s2 = v0*v0+v1*v1+v2*v2+v3*v3;
                #pragma unroll
                for (int o = 16; o; o >>= 1) {
                    s  += __shfl_xor_sync(0xffffffffu, s , o);
                    s2 += __shfl_xor_sync(0xffffffffu, s2, o);
                }
                float mu = s*(1.f/128.f), var = s2*(1.f/128.f) - mu*mu;
                float rstd = rsqrtf(var + 1e-5f);
                *(__half2*)&th[r*HP + 4*lane] =
                    __floats2half2_rn((v0-mu)*rstd*w2v.x + b2v.x, (v1-mu)*rstd*w2v.y + b2v.y);
                *(__half2*)&th[r*HP + 4*lane + 2] =
                    __floats2half2_rn((v2-mu)*rstd*w2v.z + b2v.z, (v3-mu)*rstd*w2v.w + b2v.w);
            }
            {   // pair LN1 + park residual into t32 row (now free)
                float4 v = *(const float4*)&pair[(size_t)(p0 + r)*CC + 4*lane];
                float s  = v.x+v.y+v.z+v.w;
                float s2 = v.x*v.x+v.y*v.y+v.z*v.z+v.w*v.w;
                #pragma unroll
                for (int o = 16; o; o >>= 1) {
                    s  += __shfl_xor_sync(0xffffffffu, s , o);
                    s2 += __shfl_xor_sync(0xffffffffu, s2, o);
                }
                float mu = s*(1.f/128.f), var = s2*(1.f/128.f) - mu*mu;
                float rstd = rsqrtf(var + 1e-5f);
                *(__half2*)&xh[r*HP + 4*lane] =
                    __floats2half2_rn((v.x-mu)*rstd*w1v.x + b1v.x, (v.y-mu)*rstd*w1v.y + b1v.y);
                *(__half2*)&xh[r*HP + 4*lane + 2] =
                    __floats2half2_rn((v.z-mu)*rstd*w1v.z + b1v.z, (v.w-mu)*rstd*w1v.w + b1v.w);
                *(float4*)&t32[r*T32_PAD + 4*lane] = v;
            }
        }
    }

    const int wm = warp & 1;         // rows 32*wm
    const int wn = warp >> 1;        // cols 16*wn within 64-chunk
    const int gid = lane >> 2, tig = lane & 3;
    const int lrow = lane & 7;
    const int am8  = (lane >> 3) & 1;
    const int am16 = (lane >> 4) & 1;

    const uint32_t atb = sptr(th) + (uint32_t)(((32*wm + am8*8 + lrow)*HP + am16*8) * 2);
    const uint32_t axb = sptr(xh) + (uint32_t)(((32*wm + am8*8 + lrow)*HP + am16*8) * 2);
    const uint32_t bbb = whb + (uint32_t)(((16*wn + am16*8 + lrow)*HP + am8*8) * 2);

    for (int oc = 0; oc < 2; ++oc) {
        const int o0 = oc * 64;
        asm volatile("cp.async.wait_group 0;");
        __syncthreads();   // weights + (first pass) th/xh/t32 ready

        float accO[2][2][4] = {}, accG[2][2][4] = {};

        #pragma unroll
        for (int kk = 0; kk < 128; kk += 16) {
            uint32_t at[2][4], ax[2][4], bo[4], bg[4];
            ldsm4(at[0], atb + (uint32_t)(kk*2));
            ldsm4(at[1], atb + (uint32_t)((16*HP + kk)*2));
            ldsm4(ax[0], axb + (uint32_t)(kk*2));
            ldsm4(ax[1], axb + (uint32_t)((16*HP + kk)*2));
            ldsm4(bo, bbb + (uint32_t)(kk*2));
            ldsm4(bg, bbb + (uint32_t)((64*HP + kk)*2));
            #pragma unroll
            for (int mt = 0; mt < 2; ++mt)
                #pragma unroll
                for (int nt = 0; nt < 2; ++nt) {
                    mma16(accO[mt][nt], at[mt], &bo[2*nt]);
                    mma16(accG[mt][nt], ax[mt], &bg[2*nt]);
                }
        }
        __syncthreads();   // all done reading wh

        if (oc == 0) load_w(64);   // overlaps epilogue

        #pragma unroll
        for (int mt = 0; mt < 2; ++mt) {
            int rl0 = 32*wm + 16*mt + gid;
            #pragma unroll
            for (int nt = 0; nt < 2; ++nt) {
                int col = o0 + 16*wn + 8*nt + 2*tig;
                const float* O = accO[mt][nt];
                const float* G = accG[mt][nt];
                {
                    float2 pr = *(const float2*)&t32[rl0*T32_PAD + col];
                    float2 ov;
                    ov.x = pr.x + O[0] * sigm(G[0]);
                    ov.y = pr.y + O[1] * sigm(G[1]);
                    *(float2*)&out[(size_t)(p0 + rl0)*CC + col] = ov;
                }
                {
                    float2 pr = *(const float2*)&t32[(rl0+8)*T32_PAD + col];
                    float2 ov;
                    ov.x = pr.x + O[2] * sigm(G[2]);
                    ov.y = pr.y + O[3] * sigm(G[3]);
                    *(float2*)&out[(size_t)(p0 + rl0 + 8)*CC + col] = ov;
                }
            }
        }
    }
}

// ---------------------------------------------------------------------------
extern "C" void kernel_launch(void* const* d_in, const int* in_sizes, int n_in,
                              void* d_out, int out_size)
{
    const float* pair = (const float*)d_in[0];
    const float* mask = (const float*)d_in[1];
    const float* w1   = (const float*)d_in[2];
    const float* b1   = (const float*)d_in[3];
    const float* Wp   = (const float*)d_in[4];
    const float* Wg   = (const float*)d_in[5];
    const float* w2   = (const float*)d_in[6];
    const float* b2   = (const float*)d_in[7];
    const float* Wo   = (const float*)d_in[8];
    const float* Wgl  = (const float*)d_in[9];
    float* out = (float*)d_out;

    cudaFuncSetAttribute(kA, cudaFuncAttributeMaxDynamicSharedMemorySize, (int)KA_SMEM);
    cudaFuncSetAttribute(kC, cudaFuncAttributeMaxDynamicSharedMemorySize, (int)KC_SMEM);

    kW<<<128, 256>>>(Wp, Wg, Wo, Wgl);
    kA<<<NPOS/128, 256, KA_SMEM>>>(pair, mask, w1, b1);
    kB<<<dim3(NN/128, NN/128, CC), 256>>>();
    kC<<<NPOS/64, 256, KC_SMEM>>>(pair, w1, b1, w2, b2, out);
}

// round 9
// speedup vs baseline: 6.0310x; 1.0059x over previous
#include <cuda_runtime.h>
#include <cuda_fp16.h>
#include <math.h>
#include <stdint.h>

#define NN 512
#define CC 128
#define NPOS (NN*NN)

__device__ __half g_a[(size_t)CC * NPOS];
__device__ __half g_b[(size_t)CC * NPOS];
__device__ float  g_t[(size_t)CC * NPOS];

// fp16 weight copies (filled by kW once per launch)
__device__ __half g_wp[256*128];
__device__ __half g_wg[256*128];
__device__ __half g_wo[128*128];
__device__ __half g_wgl[128*128];

// ---------------------------------------------------------------------------
// helpers
// ---------------------------------------------------------------------------
__device__ __forceinline__ void mma16(float* d, const uint32_t* a, const uint32_t* b) {
    asm volatile(
        "mma.sync.aligned.m16n8k16.row.col.f32.f16.f16.f32 "
        "{%0,%1,%2,%3}, {%4,%5,%6,%7}, {%8,%9}, {%0,%1,%2,%3};\n"
        : "+f"(d[0]), "+f"(d[1]), "+f"(d[2]), "+f"(d[3])
        : "r"(a[0]), "r"(a[1]), "r"(a[2]), "r"(a[3]), "r"(b[0]), "r"(b[1]));
}
__device__ __forceinline__ void ldsm4(uint32_t* r, uint32_t addr) {
    asm volatile("ldmatrix.sync.aligned.m8n8.x4.shared.b16 {%0,%1,%2,%3}, [%4];"
                 : "=r"(r[0]), "=r"(r[1]), "=r"(r[2]), "=r"(r[3]) : "r"(addr));
}
__device__ __forceinline__ float sigm(float x) {
    return __fdividef(1.f, 1.f + __expf(-x));
}
__device__ __forceinline__ uint32_t sptr(const void* p) {
    return (uint32_t)__cvta_generic_to_shared(p);
}
__device__ __forceinline__ void cpa16(uint32_t dst, const void* src) {
    asm volatile("cp.async.cg.shared.global [%0], [%1], 16;" :: "r"(dst), "l"(src));
}

#define HP 136   // half pad: 272B rows, ldmatrix conflict-free

// ---------------------------------------------------------------------------
// kW: convert weights to fp16 once
// ---------------------------------------------------------------------------
__global__ void __launch_bounds__(256) kW(const float* __restrict__ Wp,
                                          const float* __restrict__ Wg,
                                          const float* __restrict__ Wo,
                                          const float* __restrict__ Wgl)
{
    int idx = blockIdx.x * 256 + threadIdx.x;
    g_wp[idx] = __float2half_rn(Wp[idx]);
    g_wg[idx] = __float2half_rn(Wg[idx]);
    if (idx < 16384) {
        g_wo [idx] = __float2half_rn(Wo [idx]);
        g_wgl[idx] = __float2half_rn(Wgl[idx]);
    }
}

// ---------------------------------------------------------------------------
// Kernel A: LN1 + fp16 MMA vs Wp/Wg + mask*sigmoid + split  (round-8 design)
// ---------------------------------------------------------------------------
#define KA_SMEM ((128*HP + 128*HP + 64*HP)*2 + 128*4 + 16)

__global__ void __launch_bounds__(256, 2) kA(const float* __restrict__ pair,
                                             const float* __restrict__ mask,
                                             const float* __restrict__ w1,
                                             const float* __restrict__ b1)
{
    extern __shared__ char smraw[];
    __half* xh    = (__half*)smraw;               // 128*HP
    __half* wh    = xh + 128*HP;                  // 128*HP (wp | wg chunk)
    __half* stage = wh + 128*HP;                  // 64*HP
    float*  mrow  = (float*)(stage + 64*HP);      // 128

    const int tid = threadIdx.x;
    const int p0  = blockIdx.x * 128;
    const int warp = tid >> 5, lane = tid & 31;
    const uint32_t whb = sptr(wh);

    auto load_w = [&](int o0) {
        #pragma unroll
        for (int it = 0; it < 8; ++it) {
            int idx = it*256 + tid;
            int m = idx >> 10, j = idx & 1023;
            int n = j >> 4, g = j & 15;
            const __half* src = (m ? g_wg : g_wp) + (size_t)(o0+n)*CC + g*8;
            cpa16(whb + (uint32_t)((m*64*HP + n*HP + g*8) * 2), src);
        }
        asm volatile("cp.async.commit_group;");
    };

    load_w(0);

    if (tid < 128) mrow[tid] = mask[p0 + tid];

    {
        float4 wv = *(const float4*)&w1[4*lane];
        float4 bv = *(const float4*)&b1[4*lane];
        #pragma unroll
        for (int rr = 0; rr < 16; ++rr) {
            int r = warp*16 + rr;
            float4 v = *(const float4*)&pair[(size_t)(p0 + r)*CC + 4*lane];
            float s  = v.x+v.y+v.z+v.w;
            float s2 = v.x*v.x+v.y*v.y+v.z*v.z+v.w*v.w;
            #pragma unroll
            for (int o = 16; o; o >>= 1) {
                s  += __shfl_xor_sync(0xffffffffu, s , o);
                s2 += __shfl_xor_sync(0xffffffffu, s2, o);
            }
            float mu = s*(1.f/128.f), var = s2*(1.f/128.f) - mu*mu;
            float rstd = rsqrtf(var + 1e-5f);
            *(__half2*)&xh[r*HP + 4*lane] =
                __floats2half2_rn((v.x-mu)*rstd*wv.x + bv.x, (v.y-mu)*rstd*wv.y + bv.y);
            *(__half2*)&xh[r*HP + 4*lane + 2] =
                __floats2half2_rn((v.z-mu)*rstd*wv.z + bv.z, (v.w-mu)*rstd*wv.w + bv.w);
        }
    }

    const int wm = warp & 3;
    const int wn = warp >> 2;
    const int gid = lane >> 2, tig = lane & 3;
    const int lrow = lane & 7;
    const int am8  = (lane >> 3) & 1;
    const int am16 = (lane >> 4) & 1;

    const uint32_t aab = sptr(xh) + (uint32_t)(((32*wm + am8*8 + lrow)*HP + am16*8) * 2);
    const uint32_t bab = whb + (uint32_t)(((32*wn + am16*8 + lrow)*HP + am8*8) * 2);

    for (int oc = 0; oc < 4; ++oc) {
        const int o0 = oc * 64;
        asm volatile("cp.async.wait_group 0;");
        __syncthreads();

        float accP[2][4][4] = {}, accG[2][4][4] = {};

        #pragma unroll
        for (int kk = 0; kk < 128; kk += 16) {
            uint32_t a[2][4], bp[2][4], bg[2][4];
            ldsm4(a[0], aab + (uint32_t)(kk*2));
            ldsm4(a[1], aab + (uint32_t)((16*HP + kk)*2));
            ldsm4(bp[0], bab + (uint32_t)(kk*2));
            ldsm4(bp[1], bab + (uint32_t)((16*HP + kk)*2));
            ldsm4(bg[0], bab + (uint32_t)((64*HP + kk)*2));
            ldsm4(bg[1], bab + (uint32_t)((80*HP + kk)*2));
            #pragma unroll
            for (int mt = 0; mt < 2; ++mt)
                #pragma unroll
                for (int nt = 0; nt < 4; ++nt) {
                    mma16(accP[mt][nt], a[mt], &bp[nt>>1][2*(nt&1)]);
                    mma16(accG[mt][nt], a[mt], &bg[nt>>1][2*(nt&1)]);
                }
        }
        __syncthreads();

        if (oc < 3) load_w(o0 + 64);

        #pragma unroll
        for (int mt = 0; mt < 2; ++mt) {
            int rl0 = 32*wm + 16*mt + gid;
            int rl1 = rl0 + 8;
            float m0 = mrow[rl0], m1 = mrow[rl1];
            #pragma unroll
            for (int nt = 0; nt < 4; ++nt) {
                int cl = 32*wn + 8*nt + 2*tig;
                const float* P = accP[mt][nt];
                const float* G = accG[mt][nt];
                stage[cl*HP + rl0]     = __float2half_rn(P[0] * m0 * sigm(G[0]));
                stage[(cl+1)*HP + rl0] = __float2half_rn(P[1] * m0 * sigm(G[1]));
                stage[cl*HP + rl1]     = __float2half_rn(P[2] * m1 * sigm(G[2]));
                stage[(cl+1)*HP + rl1] = __float2half_rn(P[3] * m1 * sigm(G[3]));
            }
        }
        __syncthreads();

        #pragma unroll
        for (int it = 0; it < 16; ++it) {
            int w = it*256 + tid;
            int seg = w >> 6, rw = w & 63;
            int og = o0 + seg;
            uint32_t val = *(const uint32_t*)&stage[seg*HP + 2*rw];
            __half* dst = (og & 1) ? g_b : g_a;
            *(uint32_t*)&dst[(size_t)(og >> 1)*NPOS + p0 + 2*rw] = val;
        }
        __syncthreads();
    }
}

// ---------------------------------------------------------------------------
// Kernel B: per-channel NT fp16 GEMM (unchanged)
// ---------------------------------------------------------------------------
#define KBP 40

__global__ void __launch_bounds__(256, 2) kB()
{
    const int c  = blockIdx.z;
    const __half* __restrict__ A = g_a + (size_t)c * NPOS;
    const __half* __restrict__ B = g_b + (size_t)c * NPOS;
    float* __restrict__ T = g_t + (size_t)c * NPOS;
    const int i0 = blockIdx.y * 128;
    const int j0 = blockIdx.x * 128;

    __shared__ __half As[2][128*KBP];
    __shared__ __half Bs[2][128*KBP];
    const uint32_t sA = sptr(&As[0][0]);
    const uint32_t sB = sptr(&Bs[0][0]);

    const int tid = threadIdx.x;
    const int warp = tid >> 5, lane = tid & 31;
    const int wm = warp & 1;
    const int wn = warp >> 1;
    const int gid = lane >> 2, tig = lane & 3;
    const int lrow = lane & 7;
    const int am8  = (lane >> 3) & 1;
    const int am16 = (lane >> 4) & 1;

    const uint32_t aoff = (uint32_t)(((64*wm + am8*8 + lrow)*KBP + am16*8) * 2);
    const uint32_t boff = (uint32_t)(((32*wn + am16*8 + lrow)*KBP + am8*8) * 2);
    const uint32_t bufbytes = 128*KBP*2;

    float acc[4][4][4] = {};

    auto load_chunk = [&](int buf, int k0) {
        const uint32_t bo = (uint32_t)(buf * bufbytes);
        #pragma unroll
        for (int it = 0; it < 2; ++it) {
            int idx = it*256 + tid;
            int row = idx >> 2, g = idx & 3;
            uint32_t doff = (uint32_t)(row*KBP*2 + g*16);
            cpa16(sA + bo + doff, &A[(size_t)(i0+row)*NN + k0 + g*8]);
            cpa16(sB + bo + doff, &B[(size_t)(j0+row)*NN + k0 + g*8]);
        }
        asm volatile("cp.async.commit_group;");
    };

    load_chunk(0, 0);
    load_chunk(1, 32);

    #pragma unroll 1
    for (int kt = 0; kt < 16; ++kt) {
        const int cur = kt & 1;
        if (kt < 15) asm volatile("cp.async.wait_group 1;");
        else         asm volatile("cp.async.wait_group 0;");
        __syncthreads();

        const uint32_t cb = (uint32_t)(cur * bufbytes);
        #pragma unroll
        for (int s = 0; s < 2; ++s) {
            const uint32_t ks = (uint32_t)(s * 16 * 2);
            uint32_t a[4][4], bq[2][4];
            #pragma unroll
            for (int mt = 0; mt < 4; ++mt)
                ldsm4(a[mt], sA + cb + aoff + (uint32_t)(16*mt*KBP*2) + ks);
            ldsm4(bq[0], sB + cb + boff + ks);
            ldsm4(bq[1], sB + cb + boff + (uint32_t)(16*KBP*2) + ks);
            #pragma unroll
            for (int mt = 0; mt < 4; ++mt)
                #pragma unroll
                for (int nt = 0; nt < 4; ++nt)
                    mma16(acc[mt][nt], a[mt], &bq[nt>>1][2*(nt&1)]);
        }
        __syncthreads();

        if (kt + 2 < 16) load_chunk(cur, (kt + 2) * 32);
    }

    #pragma unroll
    for (int mt = 0; mt < 4; ++mt) {
        int r0 = i0 + 64*wm + 16*mt + gid;
        #pragma unroll
        for (int nt = 0; nt < 4; ++nt) {
            int cbn = j0 + 32*wn + 8*nt + 2*tig;
            *(float2*)&T[(size_t)r0*NN + cbn]     = make_float2(acc[mt][nt][0], acc[mt][nt][1]);
            *(float2*)&T[(size_t)(r0+8)*NN + cbn] = make_float2(acc[mt][nt][2], acc[mt][nt][3]);
        }
    }
}

// ---------------------------------------------------------------------------
// Kernel C: LN2(tri)@Wo^T * sigmoid(LN1(pair)@Wgl^T) + pair
// CTA: 512 threads (16 warps), 128 positions, single pass over 128 outputs.
// smem: t32[128][132] f32 (tri -> pair residual cache),
//       wh[256*HP] h (Wo rows 0..127 | Wgl rows 128..255),
//       th[128*HP] h, xh[128*HP] h.  Total ~207 KB, 1 CTA/SM.
// ---------------------------------------------------------------------------
#define T32_PAD 132
#define KC_T32B (128*T32_PAD*4)
#define KC_SMEM (KC_T32B + (256*HP)*2 + 2*(128*HP)*2 + 16)

__global__ void __launch_bounds__(512) kC(const float* __restrict__ pair,
                                          const float* __restrict__ w1,
                                          const float* __restrict__ b1,
                                          const float* __restrict__ w2,
                                          const float* __restrict__ b2,
                                          float* __restrict__ out)
{
    extern __shared__ char smraw[];
    float*  t32 = (float*)smraw;                          // 128*132 f32
    __half* wh  = (__half*)(smraw + KC_T32B);             // 256*HP
    __half* th  = wh + 256*HP;                            // 128*HP
    __half* xh  = th + 128*HP;                            // 128*HP

    const int tid = threadIdx.x;
    const int p0  = blockIdx.x * 128;
    const int warp = tid >> 5, lane = tid & 31;
    const uint32_t whb = sptr(wh);

    // prefetch BOTH weight matrices (Wo then Wgl), 4096 x 16B chunks
    {
        #pragma unroll
        for (int it = 0; it < 8; ++it) {
            int idx = it*512 + tid;               // 0..4095
            int n = idx >> 4, g = idx & 15;
            const __half* src = (n < 128) ? (g_wo + (size_t)n*CC + g*8)
                                          : (g_wgl + (size_t)(n-128)*CC + g*8);
            cpa16(whb + (uint32_t)((n*HP + g*8) * 2), src);
        }
        asm volatile("cp.async.commit_group;");
    }

    // tri tile gather (coalesced over positions)
    #pragma unroll
    for (int it = 0; it < 32; ++it) {
        int idx = it*512 + tid;                   // 0..16383
        int r = idx & 127, c = idx >> 7;
        t32[r*T32_PAD + c] = g_t[(size_t)c*NPOS + p0 + r];
    }
    __syncthreads();

    // LN2(t32)->th (consumes row), then LN1(pair)->xh + park residual in t32
    {
        float4 w1v = *(const float4*)&w1[4*lane];
        float4 b1v = *(const float4*)&b1[4*lane];
        float4 w2v = *(const float4*)&w2[4*lane];
        float4 b2v = *(const float4*)&b2[4*lane];
        #pragma unroll
        for (int rr = 0; rr < 8; ++rr) {
            int r = warp*8 + rr;
            {
                float v0 = t32[r*T32_PAD + 4*lane    ];
                float v1 = t32[r*T32_PAD + 4*lane + 1];
                float v2 = t32[r*T32_PAD + 4*lane + 2];
                float v3 = t32[r*T32_PAD + 4*lane + 3];
                float s  = v0+v1+v2+v3;
                float s2 = v0*v0+v1*v1+v2*v2+v3*v3;
                #pragma unroll
                for (int o = 16; o; o >>= 1) {
                    s  += __shfl_xor_sync(0xffffffffu, s , o);
                    s2 += __shfl_xor_sync(0xffffffffu, s2, o);
                }
                float mu = s*(1.f/128.f), var = s2*(1.f/128.f) - mu*mu;
                float rstd = rsqrtf(var + 1e-5f);
                *(__half2*)&th[r*HP + 4*lane] =
                    __floats2half2_rn((v0-mu)*rstd*w2v.x + b2v.x, (v1-mu)*rstd*w2v.y + b2v.y);
                *(__half2*)&th[r*HP + 4*lane + 2] =
                    __floats2half2_rn((v2-mu)*rstd*w2v.z + b2v.z, (v3-mu)*rstd*w2v.w + b2v.w);
            }
            {
                float4 v = *(const float4*)&pair[(size_t)(p0 + r)*CC + 4*lane];
                float s  = v.x+v.y+v.z+v.w;
                float s2 = v.x*v.x+v.y*v.y+v.z*v.z+v.w*v.w;
                #pragma unroll
                for (int o = 16; o; o >>= 1) {
                    s  += __shfl_xor_sync(0xffffffffu, s , o);
                    s2 += __shfl_xor_sync(0xffffffffu, s2, o);
                }
                float mu = s*(1.f/128.f), var = s2*(1.f/128.f) - mu*mu;
                float rstd = rsqrtf(var + 1e-5f);
                *(__half2*)&xh[r*HP + 4*lane] =
                    __floats2half2_rn((v.x-mu)*rstd*w1v.x + b1v.x, (v.y-mu)*rstd*w1v.y + b1v.y);
                *(__half2*)&xh[r*HP + 4*lane + 2] =
                    __floats2half2_rn((v.z-mu)*rstd*w1v.z + b1v.z, (v.w-mu)*rstd*w1v.w + b1v.w);
                *(float4*)&t32[r*T32_PAD + 4*lane] = v;
            }
        }
    }
    asm volatile("cp.async.wait_group 0;");
    __syncthreads();

    // warp grid: wm 0..3 (32 rows), wn 0..3 (32 cols)
    const int wm = warp & 3;
    const int wn = warp >> 2;
    const int gid = lane >> 2, tig = lane & 3;
    const int lrow = lane & 7;
    const int am8  = (lane >> 3) & 1;
    const int am16 = (lane >> 4) & 1;

    const uint32_t atb = sptr(th) + (uint32_t)(((32*wm + am8*8 + lrow)*HP + am16*8) * 2);
    const uint32_t axb = sptr(xh) + (uint32_t)(((32*wm + am8*8 + lrow)*HP + am16*8) * 2);
    const uint32_t bob = whb + (uint32_t)(((32*wn + am16*8 + lrow)*HP + am8*8) * 2);
    const uint32_t bgb = bob + (uint32_t)(128*HP*2);

    float accO[2][4][4] = {}, accG[2][4][4] = {};

    #pragma unroll
    for (int kk = 0; kk < 128; kk += 16) {
        uint32_t at[2][4], ax[2][4], bo[2][4], bg[2][4];
        ldsm4(at[0], atb + (uint32_t)(kk*2));
        ldsm4(at[1], atb + (uint32_t)((16*HP + kk)*2));
        ldsm4(ax[0], axb + (uint32_t)(kk*2));
        ldsm4(ax[1], axb + (uint32_t)((16*HP + kk)*2));
        ldsm4(bo[0], bob + (uint32_t)(kk*2));
        ldsm4(bo[1], bob + (uint32_t)((16*HP + kk)*2));
        ldsm4(bg[0], bgb + (uint32_t)(kk*2));
        ldsm4(bg[1], bgb + (uint32_t)((16*HP + kk)*2));
        #pragma unroll
        for (int mt = 0; mt < 2; ++mt)
            #pragma unroll
            for (int nt = 0; nt < 4; ++nt) {
                mma16(accO[mt][nt], at[mt], &bo[nt>>1][2*(nt&1)]);
                mma16(accG[mt][nt], ax[mt], &bg[nt>>1][2*(nt&1)]);
            }
    }

    // epilogue: residual from parked t32, direct float2 stores
    #pragma unroll
    for (int mt = 0; mt < 2; ++mt) {
        int rl0 = 32*wm + 16*mt + gid;
        #pragma unroll
        for (int nt = 0; nt < 4; ++nt) {
            int col = 32*wn + 8*nt + 2*tig;
            const float* O = accO[mt][nt];
            const float* G = accG[mt][nt];
            {
                float2 pr = *(const float2*)&t32[rl0*T32_PAD + col];
                float2 ov;
                ov.x = pr.x + O[0] * sigm(G[0]);
                ov.y = pr.y + O[1] * sigm(G[1]);
                *(float2*)&out[(size_t)(p0 + rl0)*CC + col] = ov;
            }
            {
                float2 pr = *(const float2*)&t32[(rl0+8)*T32_PAD + col];
                float2 ov;
                ov.x = pr.x + O[2] * sigm(G[2]);
                ov.y = pr.y + O[3] * sigm(G[3]);
                *(float2*)&out[(size_t)(p0 + rl0 + 8)*CC + col] = ov;
            }
        }
    }
}

// ---------------------------------------------------------------------------
extern "C" void kernel_launch(void* const* d_in, const int* in_sizes, int n_in,
                              void* d_out, int out_size)
{
    const float* pair = (const float*)d_in[0];
    const float* mask = (const float*)d_in[1];
    const float* w1   = (const float*)d_in[2];
    const float* b1   = (const float*)d_in[3];
    const float* Wp   = (const float*)d_in[4];
    const float* Wg   = (const float*)d_in[5];
    const float* w2   = (const float*)d_in[6];
    const float* b2   = (const float*)d_in[7];
    const float* Wo   = (const float*)d_in[8];
    const float* Wgl  = (const float*)d_in[9];
    float* out = (float*)d_out;

    cudaFuncSetAttribute(kA, cudaFuncAttributeMaxDynamicSharedMemorySize, (int)KA_SMEM);
    cudaFuncSetAttribute(kC, cudaFuncAttributeMaxDynamicSharedMemorySize, (int)KC_SMEM);

    kW<<<128, 256>>>(Wp, Wg, Wo, Wgl);
    kA<<<NPOS/128, 256, KA_SMEM>>>(pair, mask, w1, b1);
    kB<<<dim3(NN/128, NN/128, CC), 256>>>();
    kC<<<NPOS/128, 512, KC_SMEM>>>(pair, w1, b1, w2, b2, out);
}

// round 10
// speedup vs baseline: 6.3127x; 1.0467x over previous
#include <cuda_runtime.h>
#include <cuda_fp16.h>
#include <math.h>
#include <stdint.h>

#define NN 512
#define CC 128
#define NPOS (NN*NN)

__device__ __half g_a[(size_t)CC * NPOS];
__device__ __half g_b[(size_t)CC * NPOS];
__device__ __half g_t16[(size_t)CC * NPOS];

// fp16 weight copies (filled by kW once per launch)
__device__ __half g_wp[256*128];
__device__ __half g_wg[256*128];
__device__ __half g_wo[128*128];
__device__ __half g_wgl[128*128];

// ---------------------------------------------------------------------------
// helpers
// ---------------------------------------------------------------------------
__device__ __forceinline__ void mma16(float* d, const uint32_t* a, const uint32_t* b) {
    asm volatile(
        "mma.sync.aligned.m16n8k16.row.col.f32.f16.f16.f32 "
        "{%0,%1,%2,%3}, {%4,%5,%6,%7}, {%8,%9}, {%0,%1,%2,%3};\n"
        : "+f"(d[0]), "+f"(d[1]), "+f"(d[2]), "+f"(d[3])
        : "r"(a[0]), "r"(a[1]), "r"(a[2]), "r"(a[3]), "r"(b[0]), "r"(b[1]));
}
__device__ __forceinline__ void ldsm4(uint32_t* r, uint32_t addr) {
    asm volatile("ldmatrix.sync.aligned.m8n8.x4.shared.b16 {%0,%1,%2,%3}, [%4];"
                 : "=r"(r[0]), "=r"(r[1]), "=r"(r[2]), "=r"(r[3]) : "r"(addr));
}
__device__ __forceinline__ float sigm(float x) {
    return __fdividef(1.f, 1.f + __expf(-x));
}
__device__ __forceinline__ uint32_t sptr(const void* p) {
    return (uint32_t)__cvta_generic_to_shared(p);
}
__device__ __forceinline__ void cpa16(uint32_t dst, const void* src) {
    asm volatile("cp.async.cg.shared.global [%0], [%1], 16;" :: "r"(dst), "l"(src));
}

#define HP 136   // half pad: 272B rows, ldmatrix conflict-free

// ---------------------------------------------------------------------------
// kW: convert weights to fp16 once
// ---------------------------------------------------------------------------
__global__ void __launch_bounds__(256) kW(const float* __restrict__ Wp,
                                          const float* __restrict__ Wg,
                                          const float* __restrict__ Wo,
                                          const float* __restrict__ Wgl)
{
    int idx = blockIdx.x * 256 + threadIdx.x;
    g_wp[idx] = __float2half_rn(Wp[idx]);
    g_wg[idx] = __float2half_rn(Wg[idx]);
    if (idx < 16384) {
        g_wo [idx] = __float2half_rn(Wo [idx]);
        g_wgl[idx] = __float2half_rn(Wgl[idx]);
    }
}

// ---------------------------------------------------------------------------
// Kernel A: LN1 + fp16 MMA vs Wp/Wg + mask*sigmoid + split  (unchanged)
// ---------------------------------------------------------------------------
#define KA_SMEM ((128*HP + 128*HP + 64*HP)*2 + 128*4 + 16)

__global__ void __launch_bounds__(256, 2) kA(const float* __restrict__ pair,
                                             const float* __restrict__ mask,
                                             const float* __restrict__ w1,
                                             const float* __restrict__ b1)
{
    extern __shared__ char smraw[];
    __half* xh    = (__half*)smraw;               // 128*HP
    __half* wh    = xh + 128*HP;                  // 128*HP (wp | wg chunk)
    __half* stage = wh + 128*HP;                  // 64*HP
    float*  mrow  = (float*)(stage + 64*HP);      // 128

    const int tid = threadIdx.x;
    const int p0  = blockIdx.x * 128;
    const int warp = tid >> 5, lane = tid & 31;
    const uint32_t whb = sptr(wh);

    auto load_w = [&](int o0) {
        #pragma unroll
        for (int it = 0; it < 8; ++it) {
            int idx = it*256 + tid;
            int m = idx >> 10, j = idx & 1023;
            int n = j >> 4, g = j & 15;
            const __half* src = (m ? g_wg : g_wp) + (size_t)(o0+n)*CC + g*8;
            cpa16(whb + (uint32_t)((m*64*HP + n*HP + g*8) * 2), src);
        }
        asm volatile("cp.async.commit_group;");
    };

    load_w(0);

    if (tid < 128) mrow[tid] = mask[p0 + tid];

    {
        float4 wv = *(const float4*)&w1[4*lane];
        float4 bv = *(const float4*)&b1[4*lane];
        #pragma unroll
        for (int rr = 0; rr < 16; ++rr) {
            int r = warp*16 + rr;
            float4 v = *(const float4*)&pair[(size_t)(p0 + r)*CC + 4*lane];
            float s  = v.x+v.y+v.z+v.w;
            float s2 = v.x*v.x+v.y*v.y+v.z*v.z+v.w*v.w;
            #pragma unroll
            for (int o = 16; o; o >>= 1) {
                s  += __shfl_xor_sync(0xffffffffu, s , o);
                s2 += __shfl_xor_sync(0xffffffffu, s2, o);
            }
            float mu = s*(1.f/128.f), var = s2*(1.f/128.f) - mu*mu;
            float rstd = rsqrtf(var + 1e-5f);
            *(__half2*)&xh[r*HP + 4*lane] =
                __floats2half2_rn((v.x-mu)*rstd*wv.x + bv.x, (v.y-mu)*rstd*wv.y + bv.y);
            *(__half2*)&xh[r*HP + 4*lane + 2] =
                __floats2half2_rn((v.z-mu)*rstd*wv.z + bv.z, (v.w-mu)*rstd*wv.w + bv.w);
        }
    }

    const int wm = warp & 3;
    const int wn = warp >> 2;
    const int gid = lane >> 2, tig = lane & 3;
    const int lrow = lane & 7;
    const int am8  = (lane >> 3) & 1;
    const int am16 = (lane >> 4) & 1;

    const uint32_t aab = sptr(xh) + (uint32_t)(((32*wm + am8*8 + lrow)*HP + am16*8) * 2);
    const uint32_t bab = whb + (uint32_t)(((32*wn + am16*8 + lrow)*HP + am8*8) * 2);

    for (int oc = 0; oc < 4; ++oc) {
        const int o0 = oc * 64;
        asm volatile("cp.async.wait_group 0;");
        __syncthreads();

        float accP[2][4][4] = {}, accG[2][4][4] = {};

        #pragma unroll
        for (int kk = 0; kk < 128; kk += 16) {
            uint32_t a[2][4], bp[2][4], bg[2][4];
            ldsm4(a[0], aab + (uint32_t)(kk*2));
            ldsm4(a[1], aab + (uint32_t)((16*HP + kk)*2));
            ldsm4(bp[0], bab + (uint32_t)(kk*2));
            ldsm4(bp[1], bab + (uint32_t)((16*HP + kk)*2));
            ldsm4(bg[0], bab + (uint32_t)((64*HP + kk)*2));
            ldsm4(bg[1], bab + (uint32_t)((80*HP + kk)*2));
            #pragma unroll
            for (int mt = 0; mt < 2; ++mt)
                #pragma unroll
                for (int nt = 0; nt < 4; ++nt) {
                    mma16(accP[mt][nt], a[mt], &bp[nt>>1][2*(nt&1)]);
                    mma16(accG[mt][nt], a[mt], &bg[nt>>1][2*(nt&1)]);
                }
        }
        __syncthreads();

        if (oc < 3) load_w(o0 + 64);

        #pragma unroll
        for (int mt = 0; mt < 2; ++mt) {
            int rl0 = 32*wm + 16*mt + gid;
            int rl1 = rl0 + 8;
            float m0 = mrow[rl0], m1 = mrow[rl1];
            #pragma unroll
            for (int nt = 0; nt < 4; ++nt) {
                int cl = 32*wn + 8*nt + 2*tig;
                const float* P = accP[mt][nt];
                const float* G = accG[mt][nt];
                stage[cl*HP + rl0]     = __float2half_rn(P[0] * m0 * sigm(G[0]));
                stage[(cl+1)*HP + rl0] = __float2half_rn(P[1] * m0 * sigm(G[1]));
                stage[cl*HP + rl1]     = __float2half_rn(P[2] * m1 * sigm(G[2]));
                stage[(cl+1)*HP + rl1] = __float2half_rn(P[3] * m1 * sigm(G[3]));
            }
        }
        __syncthreads();

        #pragma unroll
        for (int it = 0; it < 16; ++it) {
            int w = it*256 + tid;
            int seg = w >> 6, rw = w & 63;
            int og = o0 + seg;
            uint32_t val = *(const uint32_t*)&stage[seg*HP + 2*rw];
            __half* dst = (og & 1) ? g_b : g_a;
            *(uint32_t*)&dst[(size_t)(og >> 1)*NPOS + p0 + 2*rw] = val;
        }
        __syncthreads();
    }
}

// ---------------------------------------------------------------------------
// Kernel B: per-channel NT fp16 GEMM, fp16 tri output
// ---------------------------------------------------------------------------
#define KBP 40

__global__ void __launch_bounds__(256, 2) kB()
{
    const int c  = blockIdx.z;
    const __half* __restrict__ A = g_a + (size_t)c * NPOS;
    const __half* __restrict__ B = g_b + (size_t)c * NPOS;
    __half* __restrict__ T = g_t16 + (size_t)c * NPOS;
    const int i0 = blockIdx.y * 128;
    const int j0 = blockIdx.x * 128;

    __shared__ __half As[2][128*KBP];
    __shared__ __half Bs[2][128*KBP];
    const uint32_t sA = sptr(&As[0][0]);
    const uint32_t sB = sptr(&Bs[0][0]);

    const int tid = threadIdx.x;
    const int warp = tid >> 5, lane = tid & 31;
    const int wm = warp & 1;
    const int wn = warp >> 1;
    const int gid = lane >> 2, tig = lane & 3;
    const int lrow = lane & 7;
    const int am8  = (lane >> 3) & 1;
    const int am16 = (lane >> 4) & 1;

    const uint32_t aoff = (uint32_t)(((64*wm + am8*8 + lrow)*KBP + am16*8) * 2);
    const uint32_t boff = (uint32_t)(((32*wn + am16*8 + lrow)*KBP + am8*8) * 2);
    const uint32_t bufbytes = 128*KBP*2;

    float acc[4][4][4] = {};

    auto load_chunk = [&](int buf, int k0) {
        const uint32_t bo = (uint32_t)(buf * bufbytes);
        #pragma unroll
        for (int it = 0; it < 2; ++it) {
            int idx = it*256 + tid;
            int row = idx >> 2, g = idx & 3;
            uint32_t doff = (uint32_t)(row*KBP*2 + g*16);
            cpa16(sA + bo + doff, &A[(size_t)(i0+row)*NN + k0 + g*8]);
            cpa16(sB + bo + doff, &B[(size_t)(j0+row)*NN + k0 + g*8]);
        }
        asm volatile("cp.async.commit_group;");
    };

    load_chunk(0, 0);
    load_chunk(1, 32);

    #pragma unroll 1
    for (int kt = 0; kt < 16; ++kt) {
        const int cur = kt & 1;
        if (kt < 15) asm volatile("cp.async.wait_group 1;");
        else         asm volatile("cp.async.wait_group 0;");
        __syncthreads();

        const uint32_t cb = (uint32_t)(cur * bufbytes);
        #pragma unroll
        for (int s = 0; s < 2; ++s) {
            const uint32_t ks = (uint32_t)(s * 16 * 2);
            uint32_t a[4][4], bq[2][4];
            #pragma unroll
            for (int mt = 0; mt < 4; ++mt)
                ldsm4(a[mt], sA + cb + aoff + (uint32_t)(16*mt*KBP*2) + ks);
            ldsm4(bq[0], sB + cb + boff + ks);
            ldsm4(bq[1], sB + cb + boff + (uint32_t)(16*KBP*2) + ks);
            #pragma unroll
            for (int mt = 0; mt < 4; ++mt)
                #pragma unroll
                for (int nt = 0; nt < 4; ++nt)
                    mma16(acc[mt][nt], a[mt], &bq[nt>>1][2*(nt&1)]);
        }
        __syncthreads();

        if (kt + 2 < 16) load_chunk(cur, (kt + 2) * 32);
    }

    #pragma unroll
    for (int mt = 0; mt < 4; ++mt) {
        int r0 = i0 + 64*wm + 16*mt + gid;
        #pragma unroll
        for (int nt = 0; nt < 4; ++nt) {
            int cbn = j0 + 32*wn + 8*nt + 2*tig;
            *(__half2*)&T[(size_t)r0*NN + cbn]     = __floats2half2_rn(acc[mt][nt][0], acc[mt][nt][1]);
            *(__half2*)&T[(size_t)(r0+8)*NN + cbn] = __floats2half2_rn(acc[mt][nt][2], acc[mt][nt][3]);
        }
    }
}

// ---------------------------------------------------------------------------
// Kernel C: LN2(tri)@Wo^T * sigmoid(LN1(pair)@Wgl^T) + pair
// CTA: 256 threads (8 warps), 64 positions, 2 CTAs/SM.
// Both weight matrices resident; tri gathered as fp16 directly into th,
// LN2 in place; residual re-read from pair (L2-hot).
// smem: wh[256*HP] h (Wo|Wgl), th[64*HP] h, xh[64*HP] h  = ~104.5 KB
// ---------------------------------------------------------------------------
#define KC_SMEM ((256*HP + 2*64*HP)*2 + 16)

__global__ void __launch_bounds__(256, 2) kC(const float* __restrict__ pair,
                                             const float* __restrict__ w1,
                                             const float* __restrict__ b1,
                                             const float* __restrict__ w2,
                                             const float* __restrict__ b2,
                                             float* __restrict__ out)
{
    extern __shared__ char smraw[];
    __half* wh = (__half*)smraw;                 // 256*HP (Wo rows | Wgl rows)
    __half* th = wh + 256*HP;                    // 64*HP
    __half* xh = th + 64*HP;                     // 64*HP

    const int tid = threadIdx.x;
    const int p0  = blockIdx.x * 64;
    const int warp = tid >> 5, lane = tid & 31;
    const uint32_t whb = sptr(wh);

    // prefetch BOTH weight matrices
    {
        #pragma unroll
        for (int it = 0; it < 16; ++it) {
            int idx = it*256 + tid;               // 0..4095
            int n = idx >> 4, g = idx & 15;
            const __half* src = (n < 128) ? (g_wo + (size_t)n*CC + g*8)
                                          : (g_wgl + (size_t)(n-128)*CC + g*8);
            cpa16(whb + (uint32_t)((n*HP + g*8) * 2), src);
        }
        asm volatile("cp.async.commit_group;");
    }

    // tri gather: fp16 plane-major -> th[r][c] (transpose via registers)
    #pragma unroll
    for (int it = 0; it < 16; ++it) {
        int idx = it*256 + tid;                   // 0..4095 (pos-pair, channel)
        int rw = idx & 31, c = idx >> 5;
        uint32_t v = *(const uint32_t*)&g_t16[(size_t)c*NPOS + p0 + 2*rw];
        __half2 h = *(__half2*)&v;
        th[(2*rw)*HP + c]   = __low2half(h);
        th[(2*rw+1)*HP + c] = __high2half(h);
    }
    __syncthreads();

    // LN2 in place on th; LN1 from pair -> xh
    {
        float4 w1v = *(const float4*)&w1[4*lane];
        float4 b1v = *(const float4*)&b1[4*lane];
        float4 w2v = *(const float4*)&w2[4*lane];
        float4 b2v = *(const float4*)&b2[4*lane];
        #pragma unroll
        for (int rr = 0; rr < 8; ++rr) {
            int r = warp*8 + rr;
            {   // tri LN2 (fp16 in, fp32 stats, fp16 out in place)
                __half2 h0 = *(__half2*)&th[r*HP + 4*lane];
                __half2 h1 = *(__half2*)&th[r*HP + 4*lane + 2];
                float v0 = __low2float(h0), v1 = __high2float(h0);
                float v2 = __low2float(h1), v3 = __high2float(h1);
                float s  = v0+v1+v2+v3;
                float s2 = v0*v0+v1*v1+v2*v2+v3*v3;
                #pragma unroll
                for (int o = 16; o; o >>= 1) {
                    s  += __shfl_xor_sync(0xffffffffu, s , o);
                    s2 += __shfl_xor_sync(0xffffffffu, s2, o);
                }
                float mu = s*(1.f/128.f), var = s2*(1.f/128.f) - mu*mu;
                float rstd = rsqrtf(var + 1e-5f);
                *(__half2*)&th[r*HP + 4*lane] =
                    __floats2half2_rn((v0-mu)*rstd*w2v.x + b2v.x, (v1-mu)*rstd*w2v.y + b2v.y);
                *(__half2*)&th[r*HP + 4*lane + 2] =
                    __floats2half2_rn((v2-mu)*rstd*w2v.z + b2v.z, (v3-mu)*rstd*w2v.w + b2v.w);
            }
            {   // pair LN1
                float4 v = *(const float4*)&pair[(size_t)(p0 + r)*CC + 4*lane];
                float s  = v.x+v.y+v.z+v.w;
                float s2 = v.x*v.x+v.y*v.y+v.z*v.z+v.w*v.w;
                #pragma unroll
                for (int o = 16; o; o >>= 1) {
                    s  += __shfl_xor_sync(0xffffffffu, s , o);
                    s2 += __shfl_xor_sync(0xffffffffu, s2, o);
                }
                float mu = s*(1.f/128.f), var = s2*(1.f/128.f) - mu*mu;
                float rstd = rsqrtf(var + 1e-5f);
                *(__half2*)&xh[r*HP + 4*lane] =
                    __floats2half2_rn((v.x-mu)*rstd*w1v.x + b1v.x, (v.y-mu)*rstd*w1v.y + b1v.y);
                *(__half2*)&xh[r*HP + 4*lane + 2] =
                    __floats2half2_rn((v.z-mu)*rstd*w1v.z + b1v.z, (v.w-mu)*rstd*w1v.w + b1v.w);
            }
        }
    }
    asm volatile("cp.async.wait_group 0;");
    __syncthreads();

    // warp grid: wm 0..1 (32 rows), wn 0..3 (32 cols)
    const int wm = warp & 1;
    const int wn = warp >> 1;
    const int gid = lane >> 2, tig = lane & 3;
    const int lrow = lane & 7;
    const int am8  = (lane >> 3) & 1;
    const int am16 = (lane >> 4) & 1;

    const uint32_t atb = sptr(th) + (uint32_t)(((32*wm + am8*8 + lrow)*HP + am16*8) * 2);
    const uint32_t axb = sptr(xh) + (uint32_t)(((32*wm + am8*8 + lrow)*HP + am16*8) * 2);
    const uint32_t bob = whb + (uint32_t)(((32*wn + am16*8 + lrow)*HP + am8*8) * 2);
    const uint32_t bgb = bob + (uint32_t)(128*HP*2);

    float accO[2][4][4] = {}, accG[2][4][4] = {};

    #pragma unroll
    for (int kk = 0; kk < 128; kk += 16) {
        uint32_t at[2][4], ax[2][4], bo[2][4], bg[2][4];
        ldsm4(at[0], atb + (uint32_t)(kk*2));
        ldsm4(at[1], atb + (uint32_t)((16*HP + kk)*2));
        ldsm4(ax[0], axb + (uint32_t)(kk*2));
        ldsm4(ax[1], axb + (uint32_t)((16*HP + kk)*2));
        ldsm4(bo[0], bob + (uint32_t)(kk*2));
        ldsm4(bo[1], bob + (uint32_t)((16*HP + kk)*2));
        ldsm4(bg[0], bgb + (uint32_t)(kk*2));
        ldsm4(bg[1], bgb + (uint32_t)((16*HP + kk)*2));
        #pragma unroll
        for (int mt = 0; mt < 2; ++mt)
            #pragma unroll
            for (int nt = 0; nt < 4; ++nt) {
                mma16(accO[mt][nt], at[mt], &bo[nt>>1][2*(nt&1)]);
                mma16(accG[mt][nt], ax[mt], &bg[nt>>1][2*(nt&1)]);
            }
    }

    // epilogue: residual re-read from pair (L2-hot), float2 stores
    #pragma unroll
    for (int mt = 0; mt < 2; ++mt) {
        int rl0 = 32*wm + 16*mt + gid;
        #pragma unroll
        for (int nt = 0; nt < 4; ++nt) {
            int col = 32*wn + 8*nt + 2*tig;
            const float* O = accO[mt][nt];
            const float* G = accG[mt][nt];
            {
                size_t a0 = (size_t)(p0 + rl0)*CC + col;
                float2 pr = *(const float2*)&pair[a0];
                float2 ov;
                ov.x = pr.x + O[0] * sigm(G[0]);
                ov.y = pr.y + O[1] * sigm(G[1]);
                *(float2*)&out[a0] = ov;
            }
            {
                size_t a1 = (size_t)(p0 + rl0 + 8)*CC + col;
                float2 pr = *(const float2*)&pair[a1];
                float2 ov;
                ov.x = pr.x + O[2] * sigm(G[2]);
                ov.y = pr.y + O[3] * sigm(G[3]);
                *(float2*)&out[a1] = ov;
            }
        }
    }
}

// ---------------------------------------------------------------------------
extern "C" void kernel_launch(void* const* d_in, const int* in_sizes, int n_in,
                              void* d_out, int out_size)
{
    const float* pair = (const float*)d_in[0];
    const float* mask = (const float*)d_in[1];
    const float* w1   = (const float*)d_in[2];
    const float* b1   = (const float*)d_in[3];
    const float* Wp   = (const float*)d_in[4];
    const float* Wg   = (const float*)d_in[5];
    const float* w2   = (const float*)d_in[6];
    const float* b2   = (const float*)d_in[7];
    const float* Wo   = (const float*)d_in[8];
    const float* Wgl  = (const float*)d_in[9];
    float* out = (float*)d_out;

    cudaFuncSetAttribute(kA, cudaFuncAttributeMaxDynamicSharedMemorySize, (int)KA_SMEM);
    cudaFuncSetAttribute(kC, cudaFuncAttributeMaxDynamicSharedMemorySize, (int)KC_SMEM);

    kW<<<128, 256>>>(Wp, Wg, Wo, Wgl);
    kA<<<NPOS/128, 256, KA_SMEM>>>(pair, mask, w1, b1);
    kB<<<dim3(NN/128, NN/128, CC), 256>>>();
    kC<<<NPOS/64, 256, KC_SMEM>>>(pair, w1, b1, w2, b2, out);
}

// round 11
// speedup vs baseline: 6.8609x; 1.0868x over previous
#include <cuda_runtime.h>
#include <cuda_fp16.h>
#include <math.h>
#include <stdint.h>

#define NN 512
#define CC 128
#define NPOS (NN*NN)

__device__ __half g_a[(size_t)CC * NPOS];
__device__ __half g_b[(size_t)CC * NPOS];
__device__ __half g_t16[(size_t)CC * NPOS];

// fp16 weight copies (filled by kW once per launch)
__device__ __half g_wp[256*128];
__device__ __half g_wg[256*128];
__device__ __half g_wo[128*128];
__device__ __half g_wgl[128*128];

// ---------------------------------------------------------------------------
// helpers
// ---------------------------------------------------------------------------
__device__ __forceinline__ void mma16(float* d, const uint32_t* a, const uint32_t* b) {
    asm volatile(
        "mma.sync.aligned.m16n8k16.row.col.f32.f16.f16.f32 "
        "{%0,%1,%2,%3}, {%4,%5,%6,%7}, {%8,%9}, {%0,%1,%2,%3};\n"
        : "+f"(d[0]), "+f"(d[1]), "+f"(d[2]), "+f"(d[3])
        : "r"(a[0]), "r"(a[1]), "r"(a[2]), "r"(a[3]), "r"(b[0]), "r"(b[1]));
}
__device__ __forceinline__ void ldsm4(uint32_t* r, uint32_t addr) {
    asm volatile("ldmatrix.sync.aligned.m8n8.x4.shared.b16 {%0,%1,%2,%3}, [%4];"
                 : "=r"(r[0]), "=r"(r[1]), "=r"(r[2]), "=r"(r[3]) : "r"(addr));
}
__device__ __forceinline__ void ldsm4t(uint32_t* r, uint32_t addr) {
    asm volatile("ldmatrix.sync.aligned.m8n8.x4.trans.shared.b16 {%0,%1,%2,%3}, [%4];"
                 : "=r"(r[0]), "=r"(r[1]), "=r"(r[2]), "=r"(r[3]) : "r"(addr));
}
__device__ __forceinline__ float sigm(float x) {
    return __fdividef(1.f, 1.f + __expf(-x));
}
__device__ __forceinline__ uint32_t sptr(const void* p) {
    return (uint32_t)__cvta_generic_to_shared(p);
}
__device__ __forceinline__ void cpa16(uint32_t dst, const void* src) {
    asm volatile("cp.async.cg.shared.global [%0], [%1], 16;" :: "r"(dst), "l"(src));
}

#define HP 136   // half pad for row-major operand tiles
#define CMP 72   // half pad for channel-major tri tile (36 u32 = 4 mod 32)

// ---------------------------------------------------------------------------
// kW: convert weights to fp16 once
// ---------------------------------------------------------------------------
__global__ void __launch_bounds__(256) kW(const float* __restrict__ Wp,
                                          const float* __restrict__ Wg,
                                          const float* __restrict__ Wo,
                                          const float* __restrict__ Wgl)
{
    int idx = blockIdx.x * 256 + threadIdx.x;
    g_wp[idx] = __float2half_rn(Wp[idx]);
    g_wg[idx] = __float2half_rn(Wg[idx]);
    if (idx < 16384) {
        g_wo [idx] = __float2half_rn(Wo [idx]);
        g_wgl[idx] = __float2half_rn(Wgl[idx]);
    }
}

// ---------------------------------------------------------------------------
// Kernel A: LN1 + fp16 MMA vs Wp/Wg + mask*sigmoid + split (unchanged)
// ---------------------------------------------------------------------------
#define KA_SMEM ((128*HP + 128*HP + 64*HP)*2 + 128*4 + 16)

__global__ void __launch_bounds__(256, 2) kA(const float* __restrict__ pair,
                                             const float* __restrict__ mask,
                                             const float* __restrict__ w1,
                                             const float* __restrict__ b1)
{
    extern __shared__ char smraw[];
    __half* xh    = (__half*)smraw;               // 128*HP
    __half* wh    = xh + 128*HP;                  // 128*HP (wp | wg chunk)
    __half* stage = wh + 128*HP;                  // 64*HP
    float*  mrow  = (float*)(stage + 64*HP);      // 128

    const int tid = threadIdx.x;
    const int p0  = blockIdx.x * 128;
    const int warp = tid >> 5, lane = tid & 31;
    const uint32_t whb = sptr(wh);

    auto load_w = [&](int o0) {
        #pragma unroll
        for (int it = 0; it < 8; ++it) {
            int idx = it*256 + tid;
            int m = idx >> 10, j = idx & 1023;
            int n = j >> 4, g = j & 15;
            const __half* src = (m ? g_wg : g_wp) + (size_t)(o0+n)*CC + g*8;
            cpa16(whb + (uint32_t)((m*64*HP + n*HP + g*8) * 2), src);
        }
        asm volatile("cp.async.commit_group;");
    };

    load_w(0);

    if (tid < 128) mrow[tid] = mask[p0 + tid];

    {
        float4 wv = *(const float4*)&w1[4*lane];
        float4 bv = *(const float4*)&b1[4*lane];
        #pragma unroll
        for (int rr = 0; rr < 16; ++rr) {
            int r = warp*16 + rr;
            float4 v = *(const float4*)&pair[(size_t)(p0 + r)*CC + 4*lane];
            float s  = v.x+v.y+v.z+v.w;
            float s2 = v.x*v.x+v.y*v.y+v.z*v.z+v.w*v.w;
            #pragma unroll
            for (int o = 16; o; o >>= 1) {
                s  += __shfl_xor_sync(0xffffffffu, s , o);
                s2 += __shfl_xor_sync(0xffffffffu, s2, o);
            }
            float mu = s*(1.f/128.f), var = s2*(1.f/128.f) - mu*mu;
            float rstd = rsqrtf(var + 1e-5f);
            *(__half2*)&xh[r*HP + 4*lane] =
                __floats2half2_rn((v.x-mu)*rstd*wv.x + bv.x, (v.y-mu)*rstd*wv.y + bv.y);
            *(__half2*)&xh[r*HP + 4*lane + 2] =
                __floats2half2_rn((v.z-mu)*rstd*wv.z + bv.z, (v.w-mu)*rstd*wv.w + bv.w);
        }
    }

    const int wm = warp & 3;
    const int wn = warp >> 2;
    const int gid = lane >> 2, tig = lane & 3;
    const int lrow = lane & 7;
    const int am8  = (lane >> 3) & 1;
    const int am16 = (lane >> 4) & 1;

    const uint32_t aab = sptr(xh) + (uint32_t)(((32*wm + am8*8 + lrow)*HP + am16*8) * 2);
    const uint32_t bab = whb + (uint32_t)(((32*wn + am16*8 + lrow)*HP + am8*8) * 2);

    for (int oc = 0; oc < 4; ++oc) {
        const int o0 = oc * 64;
        asm volatile("cp.async.wait_group 0;");
        __syncthreads();

        float accP[2][4][4] = {}, accG[2][4][4] = {};

        #pragma unroll
        for (int kk = 0; kk < 128; kk += 16) {
            uint32_t a[2][4], bp[2][4], bg[2][4];
            ldsm4(a[0], aab + (uint32_t)(kk*2));
            ldsm4(a[1], aab + (uint32_t)((16*HP + kk)*2));
            ldsm4(bp[0], bab + (uint32_t)(kk*2));
            ldsm4(bp[1], bab + (uint32_t)((16*HP + kk)*2));
            ldsm4(bg[0], bab + (uint32_t)((64*HP + kk)*2));
            ldsm4(bg[1], bab + (uint32_t)((80*HP + kk)*2));
            #pragma unroll
            for (int mt = 0; mt < 2; ++mt)
                #pragma unroll
                for (int nt = 0; nt < 4; ++nt) {
                    mma16(accP[mt][nt], a[mt], &bp[nt>>1][2*(nt&1)]);
                    mma16(accG[mt][nt], a[mt], &bg[nt>>1][2*(nt&1)]);
                }
        }
        __syncthreads();

        if (oc < 3) load_w(o0 + 64);

        #pragma unroll
        for (int mt = 0; mt < 2; ++mt) {
            int rl0 = 32*wm + 16*mt + gid;
            int rl1 = rl0 + 8;
            float m0 = mrow[rl0], m1 = mrow[rl1];
            #pragma unroll
            for (int nt = 0; nt < 4; ++nt) {
                int cl = 32*wn + 8*nt + 2*tig;
                const float* P = accP[mt][nt];
                const float* G = accG[mt][nt];
                stage[cl*HP + rl0]     = __float2half_rn(P[0] * m0 * sigm(G[0]));
                stage[(cl+1)*HP + rl0] = __float2half_rn(P[1] * m0 * sigm(G[1]));
                stage[cl*HP + rl1]     = __float2half_rn(P[2] * m1 * sigm(G[2]));
                stage[(cl+1)*HP + rl1] = __float2half_rn(P[3] * m1 * sigm(G[3]));
            }
        }
        __syncthreads();

        #pragma unroll
        for (int it = 0; it < 16; ++it) {
            int w = it*256 + tid;
            int seg = w >> 6, rw = w & 63;
            int og = o0 + seg;
            uint32_t val = *(const uint32_t*)&stage[seg*HP + 2*rw];
            __half* dst = (og & 1) ? g_b : g_a;
            *(uint32_t*)&dst[(size_t)(og >> 1)*NPOS + p0 + 2*rw] = val;
        }
        __syncthreads();
    }
}

// ---------------------------------------------------------------------------
// Kernel B: per-channel NT fp16 GEMM, 3-stage cp.async pipeline, 1 sync/iter
// ---------------------------------------------------------------------------
#define KBP 40
#define KB_BUF (128*KBP)                 // halves per operand buffer
#define KB_SMEM (3*2*KB_BUF*2)           // 61440 bytes

__global__ void __launch_bounds__(256, 2) kB()
{
    extern __shared__ __half kbsm[];
    __half* As = kbsm;                   // 3 * KB_BUF
    __half* Bs = kbsm + 3*KB_BUF;        // 3 * KB_BUF
    const uint32_t sA = sptr(As);
    const uint32_t sB = sptr(Bs);

    const int c  = blockIdx.z;
    const __half* __restrict__ A = g_a + (size_t)c * NPOS;
    const __half* __restrict__ B = g_b + (size_t)c * NPOS;
    __half* __restrict__ T = g_t16 + (size_t)c * NPOS;
    const int i0 = blockIdx.y * 128;
    const int j0 = blockIdx.x * 128;

    const int tid = threadIdx.x;
    const int warp = tid >> 5, lane = tid & 31;
    const int wm = warp & 1;
    const int wn = warp >> 1;
    const int gid = lane >> 2, tig = lane & 3;
    const int lrow = lane & 7;
    const int am8  = (lane >> 3) & 1;
    const int am16 = (lane >> 4) & 1;

    const uint32_t aoff = (uint32_t)(((64*wm + am8*8 + lrow)*KBP + am16*8) * 2);
    const uint32_t boff = (uint32_t)(((32*wn + am16*8 + lrow)*KBP + am8*8) * 2);
    const uint32_t bufbytes = (uint32_t)(KB_BUF*2);

    float acc[4][4][4] = {};

    auto load_chunk = [&](int buf, int k0) {
        const uint32_t bo = (uint32_t)buf * bufbytes;
        #pragma unroll
        for (int it = 0; it < 2; ++it) {
            int idx = it*256 + tid;
            int row = idx >> 2, g = idx & 3;
            uint32_t doff = (uint32_t)(row*KBP*2 + g*16);
            cpa16(sA + bo + doff, &A[(size_t)(i0+row)*NN + k0 + g*8]);
            cpa16(sB + bo + doff, &B[(size_t)(j0+row)*NN + k0 + g*8]);
        }
        asm volatile("cp.async.commit_group;");
    };

    load_chunk(0, 0);
    load_chunk(1, 32);

    #pragma unroll 1
    for (int kt = 0; kt < 16; ++kt) {
        if (kt < 15) asm volatile("cp.async.wait_group 1;");
        else         asm volatile("cp.async.wait_group 0;");
        __syncthreads();

        if (kt + 2 < 16) load_chunk((kt + 2) % 3, (kt + 2) * 32);

        const uint32_t cb = (uint32_t)(kt % 3) * bufbytes;
        #pragma unroll
        for (int s = 0; s < 2; ++s) {
            const uint32_t ks = (uint32_t)(s * 16 * 2);
            uint32_t a[4][4], bq[2][4];
            #pragma unroll
            for (int mt = 0; mt < 4; ++mt)
                ldsm4(a[mt], sA + cb + aoff + (uint32_t)(16*mt*KBP*2) + ks);
            ldsm4(bq[0], sB + cb + boff + ks);
            ldsm4(bq[1], sB + cb + boff + (uint32_t)(16*KBP*2) + ks);
            #pragma unroll
            for (int mt = 0; mt < 4; ++mt)
                #pragma unroll
                for (int nt = 0; nt < 4; ++nt)
                    mma16(acc[mt][nt], a[mt], &bq[nt>>1][2*(nt&1)]);
        }
    }

    #pragma unroll
    for (int mt = 0; mt < 4; ++mt) {
        int r0 = i0 + 64*wm + 16*mt + gid;
        #pragma unroll
        for (int nt = 0; nt < 4; ++nt) {
            int cbn = j0 + 32*wn + 8*nt + 2*tig;
            *(__half2*)&T[(size_t)r0*NN + cbn]     = __floats2half2_rn(acc[mt][nt][0], acc[mt][nt][1]);
            *(__half2*)&T[(size_t)(r0+8)*NN + cbn] = __floats2half2_rn(acc[mt][nt][2], acc[mt][nt][3]);
        }
    }
}

// ---------------------------------------------------------------------------
// Kernel C: LN2(tri)@Wo^T * sigmoid(LN1(pair)@Wgl^T) + pair
// CTA: 256 threads, 64 positions, 2 CTAs/SM.
// tri kept CHANNEL-MAJOR in smem (cp.async copy, no transpose STS);
// LN2 computed channel-major; A-fragments for tri via ldmatrix.trans.
// smem: wh[256*HP], th_cm[128*CMP], xh[64*HP], rs/rq[512], w2s/b2s[128]
// ---------------------------------------------------------------------------
#define KC_SMEM ((256*HP + 128*CMP + 64*HP)*2 + (512+512+128+128)*4 + 16)

__global__ void __launch_bounds__(256, 2) kC(const float* __restrict__ pair,
                                             const float* __restrict__ w1,
                                             const float* __restrict__ b1,
                                             const float* __restrict__ w2,
                                             const float* __restrict__ b2,
                                             float* __restrict__ out)
{
    extern __shared__ char smraw[];
    __half* wh    = (__half*)smraw;               // 256*HP (Wo | Wgl)
    __half* th_cm = wh + 256*HP;                  // 128*CMP  [channel][pos]
    __half* xh    = th_cm + 128*CMP;              // 64*HP
    float*  rs    = (float*)(xh + 64*HP);         // 8*64
    float*  rq    = rs + 512;                     // 8*64
    float*  w2s   = rq + 512;                     // 128
    float*  b2s   = w2s + 128;                    // 128

    const int tid = threadIdx.x;
    const int p0  = blockIdx.x * 64;
    const int warp = tid >> 5, lane = tid & 31;
    const uint32_t whb = sptr(wh);
    const uint32_t thb = sptr(th_cm);

    // 1. async tri copy (channel-major, no transpose): 1024 x 16B
    #pragma unroll
    for (int it = 0; it < 4; ++it) {
        int idx = it*256 + tid;                   // 0..1023
        int cch = idx >> 3, g = idx & 7;
        cpa16(thb + (uint32_t)((cch*CMP + g*8) * 2),
              &g_t16[(size_t)cch*NPOS + p0 + g*8]);
    }
    asm volatile("cp.async.commit_group;");

    // 2. async weight copy (both matrices)
    #pragma unroll
    for (int it = 0; it < 16; ++it) {
        int idx = it*256 + tid;                   // 0..4095
        int n = idx >> 4, g = idx & 15;
        const __half* src = (n < 128) ? (g_wo + (size_t)n*CC + g*8)
                                      : (g_wgl + (size_t)(n-128)*CC + g*8);
        cpa16(whb + (uint32_t)((n*HP + g*8) * 2), src);
    }
    asm volatile("cp.async.commit_group;");

    // 3. w2/b2 to smem
    if (tid < 128) w2s[tid] = w2[tid];
    else           b2s[tid-128] = b2[tid-128];

    // 4. LN1(pair) -> xh (row-major)
    {
        float4 w1v = *(const float4*)&w1[4*lane];
        float4 b1v = *(const float4*)&b1[4*lane];
        #pragma unroll
        for (int rr = 0; rr < 8; ++rr) {
            int r = warp*8 + rr;
            float4 v = *(const float4*)&pair[(size_t)(p0 + r)*CC + 4*lane];
            float s  = v.x+v.y+v.z+v.w;
            float s2 = v.x*v.x+v.y*v.y+v.z*v.z+v.w*v.w;
            #pragma unroll
            for (int o = 16; o; o >>= 1) {
                s  += __shfl_xor_sync(0xffffffffu, s , o);
                s2 += __shfl_xor_sync(0xffffffffu, s2, o);
            }
            float mu = s*(1.f/128.f), var = s2*(1.f/128.f) - mu*mu;
            float rstd = rsqrtf(var + 1e-5f);
            *(__half2*)&xh[r*HP + 4*lane] =
                __floats2half2_rn((v.x-mu)*rstd*w1v.x + b1v.x, (v.y-mu)*rstd*w1v.y + b1v.y);
            *(__half2*)&xh[r*HP + 4*lane + 2] =
                __floats2half2_rn((v.z-mu)*rstd*w1v.z + b1v.z, (v.w-mu)*rstd*w1v.w + b1v.w);
        }
    }

    // 5. tri arrived
    asm volatile("cp.async.wait_group 1;");
    __syncthreads();

    // 6. LN2 channel-major: warp owns 16 channels, lane owns pos-pair (2l,2l+1)
    {
        uint32_t v[16];
        float s0=0.f, s1=0.f, q0=0.f, q1=0.f;
        #pragma unroll
        for (int i = 0; i < 16; ++i) {
            v[i] = *(const uint32_t*)&th_cm[(warp*16 + i)*CMP + 2*lane];
            __half2 h = *(__half2*)&v[i];
            float lo = __low2float(h), hi = __high2float(h);
            s0 += lo; q0 += lo*lo; s1 += hi; q1 += hi*hi;
        }
        *(float2*)&rs[warp*64 + 2*lane] = make_float2(s0, s1);
        *(float2*)&rq[warp*64 + 2*lane] = make_float2(q0, q1);
        __syncthreads();
        float S0=0.f, S1=0.f, Q0=0.f, Q1=0.f;
        #pragma unroll
        for (int w8 = 0; w8 < 8; ++w8) {
            float2 a = *(const float2*)&rs[w8*64 + 2*lane];
            float2 b = *(const float2*)&rq[w8*64 + 2*lane];
            S0 += a.x; S1 += a.y; Q0 += b.x; Q1 += b.y;
        }
        float mu0 = S0*(1.f/128.f), r0 = rsqrtf(Q0*(1.f/128.f) - mu0*mu0 + 1e-5f);
        float mu1 = S1*(1.f/128.f), r1 = rsqrtf(Q1*(1.f/128.f) - mu1*mu1 + 1e-5f);
        #pragma unroll
        for (int i = 0; i < 16; ++i) {
            int cch = warp*16 + i;
            float wv = w2s[cch], bv = b2s[cch];
            __half2 h = *(__half2*)&v[i];
            float lo = (__low2float(h)  - mu0)*r0*wv + bv;
            float hi = (__high2float(h) - mu1)*r1*wv + bv;
            *(__half2*)&th_cm[cch*CMP + 2*lane] = __floats2half2_rn(lo, hi);
        }
    }

    // 7. weights arrived + LN2 writeback visible
    asm volatile("cp.async.wait_group 0;");
    __syncthreads();

    // 8. MMA: tri A via ldmatrix.trans from channel-major; x A normal; B normal
    const int wm = warp & 1;         // rows 32*wm
    const int wn = warp >> 1;        // cols 32*wn
    const int gid = lane >> 2, tig = lane & 3;
    const int lrow = lane & 7;
    const int am8  = (lane >> 3) & 1;
    const int am16 = (lane >> 4) & 1;

    // trans: lanes0-7: k rows, pos+0; 8-15: pos+8; 16-23: k+8; 24-31: both
    const uint32_t atb = thb + (uint32_t)(((am16*8 + lrow)*CMP + 32*wm + am8*8) * 2);
    const uint32_t axb = sptr(xh) + (uint32_t)(((32*wm + am8*8 + lrow)*HP + am16*8) * 2);
    const uint32_t bob = whb + (uint32_t)(((32*wn + am16*8 + lrow)*HP + am8*8) * 2);
    const uint32_t bgb = bob + (uint32_t)(128*HP*2);

    float accO[2][4][4] = {}, accG[2][4][4] = {};

    #pragma unroll
    for (int kk = 0; kk < 128; kk += 16) {
        uint32_t at[2][4], ax[2][4], bo[2][4], bg[2][4];
        ldsm4t(at[0], atb + (uint32_t)(kk*CMP*2));
        ldsm4t(at[1], atb + (uint32_t)(kk*CMP*2 + 16*2));
        ldsm4(ax[0], axb + (uint32_t)(kk*2));
        ldsm4(ax[1], axb + (uint32_t)((16*HP + kk)*2));
        ldsm4(bo[0], bob + (uint32_t)(kk*2));
        ldsm4(bo[1], bob + (uint32_t)((16*HP + kk)*2));
        ldsm4(bg[0], bgb + (uint32_t)(kk*2));
        ldsm4(bg[1], bgb + (uint32_t)((16*HP + kk)*2));
        #pragma unroll
        for (int mt = 0; mt < 2; ++mt)
            #pragma unroll
            for (int nt = 0; nt < 4; ++nt) {
                mma16(accO[mt][nt], at[mt], &bo[nt>>1][2*(nt&1)]);
                mma16(accG[mt][nt], ax[mt], &bg[nt>>1][2*(nt&1)]);
            }
    }

    // epilogue: residual from pair (L2-hot), float2 stores
    #pragma unroll
    for (int mt = 0; mt < 2; ++mt) {
        int rl0 = 32*wm + 16*mt + gid;
        #pragma unroll
        for (int nt = 0; nt < 4; ++nt) {
            int col = 32*wn + 8*nt + 2*tig;
            const float* O = accO[mt][nt];
            const float* G = accG[mt][nt];
            {
                size_t a0 = (size_t)(p0 + rl0)*CC + col;
                float2 pr = *(const float2*)&pair[a0];
                float2 ov;
                ov.x = pr.x + O[0] * sigm(G[0]);
                ov.y = pr.y + O[1] * sigm(G[1]);
                *(float2*)&out[a0] = ov;
            }
            {
                size_t a1 = (size_t)(p0 + rl0 + 8)*CC + col;
                float2 pr = *(const float2*)&pair[a1];
                float2 ov;
                ov.x = pr.x + O[2] * sigm(G[2]);
                ov.y = pr.y + O[3] * sigm(G[3]);
                *(float2*)&out[a1] = ov;
            }
        }
    }
}

// ---------------------------------------------------------------------------
extern "C" void kernel_launch(void* const* d_in, const int* in_sizes, int n_in,
                              void* d_out, int out_size)
{
    const float* pair = (const float*)d_in[0];
    const float* mask = (const float*)d_in[1];
    const float* w1   = (const float*)d_in[2];
    const float* b1   = (const float*)d_in[3];
    const float* Wp   = (const float*)d_in[4];
    const float* Wg   = (const float*)d_in[5];
    const float* w2   = (const float*)d_in[6];
    const float* b2   = (const float*)d_in[7];
    const float* Wo   = (const float*)d_in[8];
    const float* Wgl  = (const float*)d_in[9];
    float* out = (float*)d_out;

    cudaFuncSetAttribute(kA, cudaFuncAttributeMaxDynamicSharedMemorySize, (int)KA_SMEM);
    cudaFuncSetAttribute(kB, cudaFuncAttributeMaxDynamicSharedMemorySize, (int)KB_SMEM);
    cudaFuncSetAttribute(kC, cudaFuncAttributeMaxDynamicSharedMemorySize, (int)KC_SMEM);

    kW<<<128, 256>>>(Wp, Wg, Wo, Wgl);
    kA<<<NPOS/128, 256, KA_SMEM>>>(pair, mask, w1, b1);
    kB<<<dim3(NN/128, NN/128, CC), 256, KB_SMEM>>>();
    kC<<<NPOS/64, 256, KC_SMEM>>>(pair, w1, b1, w2, b2, out);
}